// round 13
// baseline (speedup 1.0000x reference)
#include <cuda_runtime.h>
#include <cuda_bf16.h>
#include <cuda_fp16.h>
#include <math.h>
#include <stdint.h>

#define BB 8
#define NQ 300
#define NKK 4096
#define EE 256
#define HH 8
#define DD 32
#define FFDIM 2048
#define LL 6
#define MQ (BB*NQ)      /* 2400 */
#define MK (BB*NKK)     /* 32768 */
#define MASKN (BB*NQ*NKK)
#define MASKW (MASKN/32)
#define ATT_SCALE 0.17677669529663687f  /* 32^-0.5 */

#if defined(__CUDA_ARCH_FEAT_SM103_ALL) || defined(__CUDA_ARCH_FEAT_SM100_ALL) || \
    (defined(__CUDA_ARCH_SPECIFIC__) && (__CUDA_ARCH_SPECIFIC__ == 1030 || __CUDA_ARCH_SPECIFIC__ == 1000))
#define HAS_TC 1
#else
#define HAS_TC 0
#endif

/* weight bank cumulative offsets (elements).
   [OFF_KV, OFF_CAWO) = combined cross-attn K/V weights:
   3072 rows x 256 = [K_l0..K_l5, V_l0..V_l5]. */
#define OFF_QKV   0
#define OFF_SAWO  1179648
#define OFF_CAWQ  1572864
#define OFF_KV    1966080
#define OFF_CAWO  2752512
#define OFF_FW1   3145728
#define OFF_FW2   6291456
#define WTOT      9437184

#define SWZ128(o) ((o) ^ (((o) >> 3) & 0x70))

/* packed operand layout: 16KB image per (tile128, kchunk32); row = [32 hi | 32 lo] bf16 */
__device__ __host__ __forceinline__ size_t pk_img(int m, int k, int K)
{
    return ((size_t)(m >> 7) * (K >> 5) + (k >> 5)) * 16384;
}
__device__ __host__ __forceinline__ uint32_t pk_off(int m, int k)
{
    return (uint32_t)((m & 127) * 128 + ((k & 31) >> 3) * 16 + (k & 7) * 2);
}

/* ------------ scratch (static device allocations only) ------------ */
__device__ __align__(256) float g_t[MQ*EE];
__device__ __align__(256) float g_sub[MQ*EE];
__device__ __align__(256) float g_kvbias[3072];
__device__ __align__(256) uint32_t g_maskbits[MASKW];
__device__ __align__(256) char g_wp[(size_t)WTOT*4];      /* packed weights (hi+lo) */
__device__ __align__(256) char g_tp[19*8*16384];          /* packed t    (K=256)   */
__device__ __align__(256) char g_ctxp[19*8*16384];        /* packed ctx  (K=256)   */
__device__ __align__(256) char g_memp[(size_t)256*8*16384];/* packed mem (K=256)   */
__device__ __align__(256) char g_ffp[(size_t)19*64*16384]; /* packed ff  (K=2048)  */
__device__ __align__(256) __half g_qkvh[MQ*3*EE], g_qkvl[MQ*3*EE];
__device__ __align__(256) __half g_cqh[MQ*EE], g_cql[MQ*EE];
__device__ __align__(256) __half g_kvh[(size_t)MK*3072];  /* cols [0,1536)=K hi, [1536,3072)=V */
__device__ __align__(256) __half g_kvl[(size_t)MK*3072];  /* K lo */

/* gemm smem layout */
#define GS_STAGE 32768
#define GS_W 16384
#define G_HDR 1024
#define G_IDESC 0x8200490u   /* f32 acc, bf16 a/b, N=128, M=128 */

#if HAS_TC
__device__ __forceinline__ uint32_t smem_u32(const void* p)
{
    uint32_t a;
    asm("{ .reg .u64 t; cvta.to.shared.u64 t, %1; cvt.u32.u64 %0, t; }"
        : "=r"(a) : "l"(p));
    return a;
}

static __device__ __forceinline__ uint64_t make_desc_sw128(uint32_t addr)
{
    const uint64_t base =
        (uint64_t(2)  << 61) | (uint64_t(1) << 46) |
        (uint64_t(64) << 32) | (uint64_t(1) << 16);
    return base | ((uint64_t)(addr >> 4) & 0x3FFF);
}

#define TC_ALLOC(sa, n) \
    asm volatile("tcgen05.alloc.cta_group::1.sync.aligned.shared::cta.b32 [%0], %1;" \
                 :: "r"(sa), "r"((uint32_t)(n)) : "memory")
#define TC_DEALLOC(t, n) \
    asm volatile("tcgen05.dealloc.cta_group::1.sync.aligned.b32 %0, %1;" :: "r"(t), "r"((uint32_t)(n)))
#define TC_COMMIT(mb) \
    asm volatile("tcgen05.commit.cta_group::1.mbarrier::arrive::one.shared::cluster.b64 [%0];" \
                 :: "r"(mb) : "memory")
#define TC_FENCE_AFTER()  asm volatile("tcgen05.fence::after_thread_sync;" ::: "memory")
#define TC_WAIT_LD()      asm volatile("tcgen05.wait::ld.sync.aligned;" ::: "memory")
#define MBAR_INVAL(mb) \
    asm volatile("mbarrier.inval.shared.b64 [%0];" :: "r"(mb) : "memory")
#define MBAR_INIT(mb, cnt) \
    asm volatile("mbarrier.init.shared.b64 [%0], %1;" :: "r"(mb), "r"((uint32_t)(cnt)) : "memory")
#define MBAR_ARRIVE_TX(mb, n) \
    asm volatile("mbarrier.arrive.expect_tx.shared.b64 _, [%0], %1;" \
                 :: "r"(mb), "r"((uint32_t)(n)) : "memory")
#define BULK_G2S(dst, src, n, mb) \
    asm volatile("cp.async.bulk.shared::cluster.global.mbarrier::complete_tx::bytes [%0], [%1], %2, [%3];" \
                 :: "r"(dst), "l"(src), "r"((uint32_t)(n)), "r"(mb) : "memory")
#define MBAR_WAIT(mb, ph) do {                                                   \
    uint32_t _mb = (mb), _ph = (ph), _done;                                      \
    asm volatile(                                                                \
        "{\n\t.reg .pred p;\n\t"                                                 \
        "mbarrier.try_wait.parity.acquire.cta.shared::cta.b64 p, [%1], %2;\n\t"  \
        "selp.b32 %0, 1, 0, p;\n\t}"                                             \
        : "=r"(_done) : "r"(_mb), "r"(_ph) : "memory");                          \
    if (!_done) {                                                                \
        asm volatile(                                                            \
            "{\n\t.reg .pred P1;\n\t"                                            \
            "WL_%=:\n\t"                                                         \
            "mbarrier.try_wait.parity.acquire.cta.shared::cta.b64 P1, [%0], %1, 0x989680;\n\t" \
            "@P1 bra.uni WD_%=;\n\t"                                             \
            "bra.uni WL_%=;\n\t"                                                 \
            "WD_%=:\n\t}"                                                        \
            :: "r"(_mb), "r"(_ph) : "memory");                                   \
    }                                                                            \
} while (0)

__device__ __forceinline__ void tc_mma_f16_ss(
    uint32_t d_tmem, uint64_t a_desc, uint64_t b_desc, uint32_t idesc, uint32_t en)
{
    asm volatile(
        "{\n\t.reg .pred p;\n\t"
        "setp.ne.u32 p, %5, 0;\n\t"
        "tcgen05.mma.cta_group::1.kind::f16 [%0], %1, %2, %3, {%4,%4,%4,%4}, p;\n\t}"
        :: "r"(d_tmem), "l"(a_desc), "l"(b_desc), "r"(idesc), "r"(0u), "r"(en)
        : "memory");
}

#define TC_LD_X32(r, ta) \
    asm volatile( \
        "tcgen05.ld.sync.aligned.32x32b.x32.b32 " \
        "{%0, %1, %2, %3, %4, %5, %6, %7, " \
        " %8, %9, %10, %11, %12, %13, %14, %15, " \
        " %16, %17, %18, %19, %20, %21, %22, %23, " \
        " %24, %25, %26, %27, %28, %29, %30, %31}, [%32];" \
        : "=r"((r)[0]),  "=r"((r)[1]),  "=r"((r)[2]),  "=r"((r)[3]), \
          "=r"((r)[4]),  "=r"((r)[5]),  "=r"((r)[6]),  "=r"((r)[7]), \
          "=r"((r)[8]),  "=r"((r)[9]),  "=r"((r)[10]), "=r"((r)[11]), \
          "=r"((r)[12]), "=r"((r)[13]), "=r"((r)[14]), "=r"((r)[15]), \
          "=r"((r)[16]), "=r"((r)[17]), "=r"((r)[18]), "=r"((r)[19]), \
          "=r"((r)[20]), "=r"((r)[21]), "=r"((r)[22]), "=r"((r)[23]), \
          "=r"((r)[24]), "=r"((r)[25]), "=r"((r)[26]), "=r"((r)[27]), \
          "=r"((r)[28]), "=r"((r)[29]), "=r"((r)[30]), "=r"((r)[31]) \
        : "r"(ta))
#endif /* HAS_TC */

/* ======================= GEMM =======================
   C = A @ W^T + bias with pre-packed bf16 hi/lo operands; hh+hl+lh in fp32 TMEM.
   128x128 CTA tile, K-chunk 32, bulk-copy pipeline driven by ONE thread.
   Outputs: optional f32, packed bf16 (cbK geometry), f16 hi(/lo < lo_ncols). */
template<int STAGES>
__global__ __launch_bounds__(256) void gemm_tc(
    const char* __restrict__ Ap, const char* __restrict__ Wp,
    const float* __restrict__ bias,
    float* __restrict__ Cf, char* __restrict__ Cbp,
    __half* __restrict__ Cfh, __half* __restrict__ Cfl,
    int M, int N, int K, int relu, int lo_ncols, int cbK)
{
#if HAS_TC
    extern __shared__ __align__(1024) char smem[];
    uint32_t sb = smem_u32(smem);
    int tid = threadIdx.x, wid = tid >> 5, lane = tid & 31;
    int mBase = blockIdx.y * 128, nBase = blockIdx.x * 128;
    int nch = K >> 5;

    if (wid == 0) { TC_ALLOC(sb, 128); }
    __syncthreads();
    uint32_t tmem;
    asm volatile("ld.shared.b32 %0, [%1];" : "=r"(tmem) : "r"(sb));
    if (tid == 0) {
        #pragma unroll
        for (int s = 0; s < STAGES; s++) {
            MBAR_INIT(sb + 8 + s * 8, 1);    /* full[s]  */
            MBAR_INIT(sb + 64 + s * 8, 1);   /* mmaDone[s] */
        }
    }
    __syncthreads();

    if (tid == 0) {
        const char* Abase = Ap + (size_t)blockIdx.y * nch * 16384;
        const char* Wbase = Wp + (size_t)blockIdx.x * nch * 16384;
        #pragma unroll
        for (int p = 0; p < 2; p++) {
            uint32_t st = sb + G_HDR + p * GS_STAGE;
            MBAR_ARRIVE_TX(sb + 8 + p * 8, 32768);
            BULK_G2S(st,        Abase + (size_t)p * 16384, 16384, sb + 8 + p * 8);
            BULK_G2S(st + GS_W, Wbase + (size_t)p * 16384, 16384, sb + 8 + p * 8);
        }
        for (int ch = 0; ch < nch; ch++) {
            int s = ch % STAGES;
            MBAR_WAIT(sb + 8 + s * 8, (uint32_t)((ch / STAGES) & 1));
            uint32_t stb = sb + G_HDR + s * GS_STAGE;
            uint64_t dA = make_desc_sw128(stb);
            uint64_t dW = make_desc_sw128(stb + GS_W);
            #pragma unroll
            for (int ks = 0; ks < 2; ks++) {
                uint64_t o = (uint64_t)(ks * 2);
                tc_mma_f16_ss(tmem, dA + o,     dW + o,     G_IDESC,
                              (ch == 0 && ks == 0) ? 0u : 1u);
                tc_mma_f16_ss(tmem, dA + o,     dW + 4 + o, G_IDESC, 1u);
                tc_mma_f16_ss(tmem, dA + 4 + o, dW + o,     G_IDESC, 1u);
            }
            TC_COMMIT(sb + 64 + s * 8);
            int pre = ch + 2;
            if (pre < nch) {
                int sp = pre % STAGES;
                int tgt = pre - STAGES;
                if (tgt >= 0)
                    MBAR_WAIT(sb + 64 + sp * 8, (uint32_t)((tgt / STAGES) & 1));
                uint32_t stp = sb + G_HDR + sp * GS_STAGE;
                MBAR_ARRIVE_TX(sb + 8 + sp * 8, 32768);
                BULK_G2S(stp,        Abase + (size_t)pre * 16384, 16384, sb + 8 + sp * 8);
                BULK_G2S(stp + GS_W, Wbase + (size_t)pre * 16384, 16384, sb + 8 + sp * 8);
            }
        }
        MBAR_WAIT(sb + 64 + ((nch - 1) % STAGES) * 8,
                  (uint32_t)(((nch - 1) / STAGES) & 1));
    }
    __syncthreads();
    TC_FENCE_AFTER();

    if (wid < 4) {
        int row = mBase + wid * 32 + lane;
        bool rv = row < M;
        #pragma unroll
        for (int cb = 0; cb < 128; cb += 32) {
            uint32_t r[32];
            TC_LD_X32(r, tmem + cb);
            TC_WAIT_LD();
            if (rv) {
                #pragma unroll
                for (int c4 = 0; c4 < 32; c4 += 4) {
                    int col = nBase + cb + c4;
                    float4 bv = *(const float4*)&bias[col];
                    float v0 = __uint_as_float(r[c4+0]) + bv.x;
                    float v1 = __uint_as_float(r[c4+1]) + bv.y;
                    float v2 = __uint_as_float(r[c4+2]) + bv.z;
                    float v3 = __uint_as_float(r[c4+3]) + bv.w;
                    if (relu) {
                        v0 = fmaxf(v0, 0.f); v1 = fmaxf(v1, 0.f);
                        v2 = fmaxf(v2, 0.f); v3 = fmaxf(v3, 0.f);
                    }
                    if (Cf)
                        *(float4*)&Cf[(size_t)row * N + col] = make_float4(v0, v1, v2, v3);
                    if (Cbp) {
                        __nv_bfloat16 h0 = __float2bfloat16(v0);
                        __nv_bfloat16 h1 = __float2bfloat16(v1);
                        __nv_bfloat16 h2 = __float2bfloat16(v2);
                        __nv_bfloat16 h3 = __float2bfloat16(v3);
                        char* d = Cbp + pk_img(row, col, cbK);
                        uint32_t off = pk_off(row, col);
                        uint32_t sh = SWZ128(off), sl = SWZ128(off + 64);
                        *(__nv_bfloat162*)(d + sh)     = __nv_bfloat162(h0, h1);
                        *(__nv_bfloat162*)(d + sh + 4) = __nv_bfloat162(h2, h3);
                        *(__nv_bfloat162*)(d + sl) = __nv_bfloat162(
                            __float2bfloat16(v0 - __bfloat162float(h0)),
                            __float2bfloat16(v1 - __bfloat162float(h1)));
                        *(__nv_bfloat162*)(d + sl + 4) = __nv_bfloat162(
                            __float2bfloat16(v2 - __bfloat162float(h2)),
                            __float2bfloat16(v3 - __bfloat162float(h3)));
                    }
                    if (Cfh) {
                        __half h0 = __float2half_rn(v0), h1 = __float2half_rn(v1);
                        __half h2 = __float2half_rn(v2), h3 = __float2half_rn(v3);
                        *(__half2*)&Cfh[(size_t)row * N + col]     = __half2(h0, h1);
                        *(__half2*)&Cfh[(size_t)row * N + col + 2] = __half2(h2, h3);
                        if (Cfl && col < lo_ncols) {
                            *(__half2*)&Cfl[(size_t)row * N + col] = __half2(
                                __float2half_rn(v0 - __half2float(h0)),
                                __float2half_rn(v1 - __half2float(h1)));
                            *(__half2*)&Cfl[(size_t)row * N + col + 2] = __half2(
                                __float2half_rn(v2 - __half2float(h2)),
                                __float2half_rn(v3 - __half2float(h3)));
                        }
                    }
                }
            }
        }
    }
    __syncthreads();
    if (tid == 0) {
        #pragma unroll
        for (int s = 0; s < STAGES; s++) {
            MBAR_INVAL(sb + 8 + s * 8);
            MBAR_INVAL(sb + 64 + s * 8);
        }
    }
    if (wid == 0) TC_DEALLOC(tmem, 128);
#else
    /* SIMT fallback for the non-accelerated gencode pass (never runs) */
    int tid = threadIdx.x;
    int tx = tid & 15, ty = tid >> 4;
    int row0 = blockIdx.y * 128 + ty * 8, col0 = blockIdx.x * 128 + tx * 8;
    float acc[8][8] = {};
    for (int k = 0; k < K; k++) {
        float a[8], w[8];
        #pragma unroll
        for (int i = 0; i < 8; i++) {
            int m = row0 + i;
            const char* d = Ap + pk_img(m, k, K);
            uint32_t off = pk_off(m, k);
            a[i] = __bfloat162float(*(const __nv_bfloat16*)(d + SWZ128(off))) +
                   __bfloat162float(*(const __nv_bfloat16*)(d + SWZ128(off + 64)));
        }
        #pragma unroll
        for (int j = 0; j < 8; j++) {
            int n = col0 + j;
            const char* d = Wp + pk_img(n, k, K);
            uint32_t off = pk_off(n, k);
            w[j] = __bfloat162float(*(const __nv_bfloat16*)(d + SWZ128(off))) +
                   __bfloat162float(*(const __nv_bfloat16*)(d + SWZ128(off + 64)));
        }
        #pragma unroll
        for (int i = 0; i < 8; i++)
            #pragma unroll
            for (int j = 0; j < 8; j++)
                acc[i][j] += a[i] * w[j];
    }
    #pragma unroll
    for (int i = 0; i < 8; i++) {
        int row = row0 + i;
        if (row >= M) break;
        #pragma unroll
        for (int j = 0; j < 8; j++) {
            int col = col0 + j;
            float v = acc[i][j] + bias[col];
            if (relu) v = fmaxf(v, 0.f);
            if (Cf) Cf[(size_t)row * N + col] = v;
            if (Cbp) {
                __nv_bfloat16 h = __float2bfloat16(v);
                char* d = Cbp + pk_img(row, col, cbK);
                uint32_t off = pk_off(row, col);
                *(__nv_bfloat16*)(d + SWZ128(off)) = h;
                *(__nv_bfloat16*)(d + SWZ128(off + 64)) =
                    __float2bfloat16(v - __bfloat162float(h));
            }
            if (Cfh) {
                __half h = __float2half_rn(v);
                Cfh[(size_t)row * N + col] = h;
                if (Cfl && col < lo_ncols)
                    Cfl[(size_t)row * N + col] = __float2half_rn(v - __half2float(h));
            }
        }
    }
#endif
}

/* ================= tensor-core flash attention (mma.sync fp16) ================= */
#define AT_QH 0
#define AT_QL 5120
#define AT_KH 10240
#define AT_KL 20480
#define AT_P  10240
#define AT_VT 30720
#define AT_S  39424
#define AT_M  73216
#define AT_L  73472
#define AT_AL 73728
#define ATT_SMEM 73984

#define MMA16816(c, a, b0, b1) \
    asm volatile("mma.sync.aligned.m16n8k16.row.col.f32.f16.f16.f32 " \
        "{%0,%1,%2,%3}, {%4,%5,%6,%7}, {%8,%9}, {%0,%1,%2,%3};" \
        : "+f"((c)[0]), "+f"((c)[1]), "+f"((c)[2]), "+f"((c)[3]) \
        : "r"((a)[0]), "r"((a)[1]), "r"((a)[2]), "r"((a)[3]), "r"(b0), "r"(b1))

__global__ __launch_bounds__(256) void attn_mma(
    const __half* __restrict__ qh_g, const __half* __restrict__ ql_g, int qstride,
    const __half* __restrict__ kh_g, const __half* __restrict__ kl_g, int kstride,
    const __half* __restrict__ vh_g, int vstride,
    const uint32_t* __restrict__ maskb,
    char* __restrict__ outp,
    int nq, int nk)
{
    extern __shared__ __align__(16) char sm[];
    __half* Qh = (__half*)(sm + AT_QH);
    __half* Ql = (__half*)(sm + AT_QL);
    __half* Kh = (__half*)(sm + AT_KH);
    __half* Kl = (__half*)(sm + AT_KL);
    __half* P  = (__half*)(sm + AT_P);
    __half* Vt = (__half*)(sm + AT_VT);
    float*  S  = (float*)(sm + AT_S);
    float*  mS = (float*)(sm + AT_M);
    float*  lS = (float*)(sm + AT_L);
    float*  aS = (float*)(sm + AT_AL);

    int tid = threadIdx.x;
    int wid = tid >> 5, lane = tid & 31;
    int gid = lane >> 2, tig = lane & 3;
    int wM = wid & 3, wHalf = wid >> 2;
    int b = blockIdx.z, hd = blockIdx.y;
    int qt = blockIdx.x * 64;

    {
        int row = tid >> 2, d8 = (tid & 3) * 8;
        uint4 vq = make_uint4(0,0,0,0), vl4 = make_uint4(0,0,0,0);
        if (qt + row < nq) {
            size_t base = ((size_t)(b * nq + qt + row)) * qstride + hd * DD + d8;
            vq  = *(const uint4*)&qh_g[base];
            vl4 = *(const uint4*)&ql_g[base];
        }
        *(uint4*)&Qh[row * 40 + d8] = vq;
        *(uint4*)&Ql[row * 40 + d8] = vl4;
    }
    if (tid < 64) { mS[tid] = -INFINITY; lS[tid] = 0.f; }
    __syncthreads();

    uint32_t aQh[2][4], aQl[2][4];
    int ar0 = wM * 16 + gid, ar1 = ar0 + 8;
    #pragma unroll
    for (int ks = 0; ks < 2; ks++) {
        int c0 = ks * 16 + 2 * tig;
        aQh[ks][0] = *(uint32_t*)&Qh[ar0 * 40 + c0];
        aQh[ks][1] = *(uint32_t*)&Qh[ar1 * 40 + c0];
        aQh[ks][2] = *(uint32_t*)&Qh[ar0 * 40 + c0 + 8];
        aQh[ks][3] = *(uint32_t*)&Qh[ar1 * 40 + c0 + 8];
        aQl[ks][0] = *(uint32_t*)&Ql[ar0 * 40 + c0];
        aQl[ks][1] = *(uint32_t*)&Ql[ar1 * 40 + c0];
        aQl[ks][2] = *(uint32_t*)&Ql[ar0 * 40 + c0 + 8];
        aQl[ks][3] = *(uint32_t*)&Ql[ar1 * 40 + c0 + 8];
    }

    float oc[4][4] = {};

    for (int kc = 0; kc < nk; kc += 128) {
        __syncthreads();

        #pragma unroll
        for (int i = 0; i < 2; i++) {
            int idx = tid + i * 256;
            int row = idx >> 2, d8 = (idx & 3) * 8;
            int kg = kc + row;
            uint4 a = make_uint4(0,0,0,0), c4 = make_uint4(0,0,0,0), vv = make_uint4(0,0,0,0);
            if (kg < nk) {
                size_t base = ((size_t)(b * nk + kg)) * kstride + hd * DD + d8;
                a  = *(const uint4*)&kh_g[base];
                c4 = *(const uint4*)&kl_g[base];
                size_t vb = ((size_t)(b * nk + kg)) * vstride + hd * DD + d8;
                vv = *(const uint4*)&vh_g[vb];
            }
            *(uint4*)&Kh[row * 40 + d8] = a;
            *(uint4*)&Kl[row * 40 + d8] = c4;
            const __half* hp = (const __half*)&vv;
            #pragma unroll
            for (int e = 0; e < 8; e++)
                Vt[(d8 + e) * 136 + row] = hp[e];
        }
        __syncthreads();

        #pragma unroll
        for (int nt = 0; nt < 8; nt++) {
            float c[4] = {0.f, 0.f, 0.f, 0.f};
            int bn = wHalf * 64 + nt * 8 + gid;
            #pragma unroll
            for (int ks = 0; ks < 2; ks++) {
                int c0 = ks * 16 + 2 * tig;
                uint32_t bh0 = *(uint32_t*)&Kh[bn * 40 + c0];
                uint32_t bh1 = *(uint32_t*)&Kh[bn * 40 + c0 + 8];
                uint32_t bl0 = *(uint32_t*)&Kl[bn * 40 + c0];
                uint32_t bl1 = *(uint32_t*)&Kl[bn * 40 + c0 + 8];
                MMA16816(c, aQh[ks], bh0, bh1);
                MMA16816(c, aQl[ks], bh0, bh1);
                MMA16816(c, aQh[ks], bl0, bl1);
            }
            int sc = wHalf * 64 + nt * 8 + 2 * tig;
            S[(wM * 16 + gid) * 132 + sc]     = c[0] * ATT_SCALE;
            S[(wM * 16 + gid) * 132 + sc + 1] = c[1] * ATT_SCALE;
            S[(wM * 16 + gid + 8) * 132 + sc]     = c[2] * ATT_SCALE;
            S[(wM * 16 + gid + 8) * 132 + sc + 1] = c[3] * ATT_SCALE;
        }
        __syncthreads();

        {
            int r = tid >> 2, j = tid & 3;
            int qrow = qt + r;
            bool rowValid = qrow < nq;
            uint32_t word = 0xFFFFFFFFu;
            if (!rowValid) word = 0u;
            else if (maskb) word = maskb[(size_t)(b * nq + qrow) * (nk >> 5) + (kc >> 5) + j];
            float mx = -INFINITY;
            #pragma unroll
            for (int e = 0; e < 32; e++) {
                int col = j * 32 + e;
                float s = S[r * 132 + col];
                bool ok = ((word >> e) & 1u) && (kc + col < nk);
                s = ok ? s : -INFINITY;
                S[r * 132 + col] = s;
                mx = fmaxf(mx, s);
            }
            mx = fmaxf(mx, __shfl_xor_sync(0xffffffffu, mx, 1));
            mx = fmaxf(mx, __shfl_xor_sync(0xffffffffu, mx, 2));
            float mOld = mS[r];
            float mNew = fmaxf(mOld, mx);
            float mUse = fmaxf(mNew, -1e30f);
            float psum = 0.f;
            #pragma unroll
            for (int e = 0; e < 32; e++) {
                int col = j * 32 + e;
                float p = __expf(S[r * 132 + col] - mUse);
                P[r * 136 + col] = __float2half_rn(p);
                psum += p;
            }
            psum += __shfl_xor_sync(0xffffffffu, psum, 1);
            psum += __shfl_xor_sync(0xffffffffu, psum, 2);
            if (j == 0) {
                float alpha = __expf(mOld - mUse);
                aS[r] = alpha;
                lS[r] = lS[r] * alpha + psum;
                mS[r] = mNew;
            }
        }
        __syncthreads();

        {
            float f0 = aS[wM * 16 + gid];
            float f1 = aS[wM * 16 + 8 + gid];
            #pragma unroll
            for (int nt = 0; nt < 4; nt++) {
                oc[nt][0] *= f0; oc[nt][1] *= f0;
                oc[nt][2] *= f1; oc[nt][3] *= f1;
            }
            #pragma unroll
            for (int ks = 0; ks < 4; ks++) {
                int kbase = wHalf * 64 + ks * 16;
                uint32_t pa[4];
                pa[0] = *(uint32_t*)&P[(wM * 16 + gid) * 136 + kbase + 2 * tig];
                pa[1] = *(uint32_t*)&P[(wM * 16 + 8 + gid) * 136 + kbase + 2 * tig];
                pa[2] = *(uint32_t*)&P[(wM * 16 + gid) * 136 + kbase + 2 * tig + 8];
                pa[3] = *(uint32_t*)&P[(wM * 16 + 8 + gid) * 136 + kbase + 2 * tig + 8];
                #pragma unroll
                for (int nt = 0; nt < 4; nt++) {
                    uint32_t b0 = *(uint32_t*)&Vt[(nt * 8 + gid) * 136 + kbase + 2 * tig];
                    uint32_t b1 = *(uint32_t*)&Vt[(nt * 8 + gid) * 136 + kbase + 2 * tig + 8];
                    MMA16816(oc[nt], pa, b0, b1);
                }
            }
        }
    }
    __syncthreads();

    float* CB = S;
    if (wHalf == 1) {
        #pragma unroll
        for (int nt = 0; nt < 4; nt++) {
            int cc = nt * 8 + 2 * tig;
            CB[(wM * 16 + gid) * 36 + cc]     = oc[nt][0];
            CB[(wM * 16 + gid) * 36 + cc + 1] = oc[nt][1];
            CB[(wM * 16 + 8 + gid) * 36 + cc]     = oc[nt][2];
            CB[(wM * 16 + 8 + gid) * 36 + cc + 1] = oc[nt][3];
        }
    }
    __syncthreads();
    if (wHalf == 0) {
        int r0 = wM * 16 + gid, r1 = r0 + 8;
        float il0 = 1.f / lS[r0], il1 = 1.f / lS[r1];
        bool v0r = (qt + r0) < nq, v1r = (qt + r1) < nq;
        #pragma unroll
        for (int nt = 0; nt < 4; nt++) {
            int cc = nt * 8 + 2 * tig;
            float x0 = (oc[nt][0] + CB[r0 * 36 + cc]) * il0;
            float x1 = (oc[nt][1] + CB[r0 * 36 + cc + 1]) * il0;
            float x2 = (oc[nt][2] + CB[r1 * 36 + cc]) * il1;
            float x3 = (oc[nt][3] + CB[r1 * 36 + cc + 1]) * il1;
            int col = hd * DD + cc;
            if (v0r) {
                int grow = b * nq + qt + r0;
                __nv_bfloat16 h0 = __float2bfloat16(x0), h1 = __float2bfloat16(x1);
                char* d = outp + pk_img(grow, col, 256);
                uint32_t off = pk_off(grow, col);
                *(__nv_bfloat162*)(d + SWZ128(off)) = __nv_bfloat162(h0, h1);
                *(__nv_bfloat162*)(d + SWZ128(off + 64)) = __nv_bfloat162(
                    __float2bfloat16(x0 - __bfloat162float(h0)),
                    __float2bfloat16(x1 - __bfloat162float(h1)));
            }
            if (v1r) {
                int grow = b * nq + qt + r1;
                __nv_bfloat16 h2 = __float2bfloat16(x2), h3 = __float2bfloat16(x3);
                char* d = outp + pk_img(grow, col, 256);
                uint32_t off = pk_off(grow, col);
                *(__nv_bfloat162*)(d + SWZ128(off)) = __nv_bfloat162(h2, h3);
                *(__nv_bfloat162*)(d + SWZ128(off + 64)) = __nv_bfloat162(
                    __float2bfloat16(x2 - __bfloat162float(h2)),
                    __float2bfloat16(x3 - __bfloat162float(h3)));
            }
        }
    }
}

/* ---------------- setup kernels ---------------- */
__global__ void mask_bits_kernel(const void* __restrict__ raw,
                                 uint32_t* __restrict__ out)
{
    __shared__ int c1, c3;
    int tid = threadIdx.x;
    if (tid == 0) { c1 = 0; c3 = 0; }
    __syncthreads();
    const unsigned char* m = (const unsigned char*)raw;
    if (m[4 * tid + 1]) atomicAdd(&c1, 1);
    if (m[4 * tid + 3]) atomicAdd(&c3, 1);
    __syncthreads();
    int mode = (c1 > 0) ? 0 : ((c3 > 0) ? 2 : 1);

    int w = blockIdx.x * blockDim.x + tid;
    if (w >= MASKW) return;
    size_t base = (size_t)w * 32;
    uint32_t bits = 0;
    if (mode == 0) {
        const unsigned char* p = (const unsigned char*)raw + base;
        #pragma unroll
        for (int e = 0; e < 32; e++) bits |= (uint32_t)(p[e] != 0) << e;
    } else if (mode == 1) {
        const int* p = (const int*)raw + base;
        #pragma unroll
        for (int e = 0; e < 32; e++) bits |= (uint32_t)(p[e] != 0) << e;
    } else {
        const float* p = (const float*)raw + base;
        #pragma unroll
        for (int e = 0; e < 32; e++) bits |= (uint32_t)(p[e] != 0.f) << e;
    }
    out[w] = bits;
}

__device__ __forceinline__ void pk_write4(char* dstbase, int n, int k, int K, float4 x)
{
    __nv_bfloat16 h0 = __float2bfloat16(x.x), h1 = __float2bfloat16(x.y);
    __nv_bfloat16 h2 = __float2bfloat16(x.z), h3 = __float2bfloat16(x.w);
    char* d = dstbase + pk_img(n, k, K);
    uint32_t off = pk_off(n, k);
    uint32_t sh = SWZ128(off), sl = SWZ128(off + 64);
    *(__nv_bfloat162*)(d + sh)     = __nv_bfloat162(h0, h1);
    *(__nv_bfloat162*)(d + sh + 4) = __nv_bfloat162(h2, h3);
    *(__nv_bfloat162*)(d + sl) = __nv_bfloat162(
        __float2bfloat16(x.x - __bfloat162float(h0)),
        __float2bfloat16(x.y - __bfloat162float(h1)));
    *(__nv_bfloat162*)(d + sl + 4) = __nv_bfloat162(
        __float2bfloat16(x.z - __bfloat162float(h2)),
        __float2bfloat16(x.w - __bfloat162float(h3)));
}

__global__ void convert_hilo_all(const float* __restrict__ tgt,
                                 const float* __restrict__ memory)
{
    int i = blockIdx.x * blockDim.x + threadIdx.x;
    int idx = i * 4;
    if (idx < MQ * EE) {
        float4 x = *(const float4*)&tgt[idx];
        pk_write4(g_tp, idx >> 8, idx & 255, 256, x);
    } else if (idx < MQ * EE + MK * EE) {
        int r = idx - MQ * EE;
        float4 x = *(const float4*)&memory[r];
        pk_write4(g_memp, r >> 8, r & 255, 256, x);
    }
}

/* weight packing; [OFF_KV, OFF_CAWO) re-laid-out as 3072 rows = [K_l0..K_l5, V_l0..V_l5] */
__global__ void convert_weights(
    const float* __restrict__ w_qkv, const float* __restrict__ w_sawo,
    const float* __restrict__ w_caq, const float* __restrict__ wk,
    const float* __restrict__ wv,   const float* __restrict__ w_cawo,
    const float* __restrict__ w_f1, const float* __restrict__ w_f2)
{
    int i = blockIdx.x * blockDim.x + threadIdx.x;
    int j = i * 4;
    if (j >= WTOT) return;
    const float* ptr;
    size_t dstbase;
    int n, k, K;
    if (j >= OFF_KV && j < OFF_CAWO) {
        int rel = j - OFF_KV;
        int r = rel >> 8, c = rel & 255;
        if (r < 1536) {
            int l = r >> 8;
            ptr = wk + (size_t)l * 65536 + (size_t)(r & 255) * 256 + c;
        } else {
            int r2 = r - 1536;
            int l = r2 >> 8;
            ptr = wv + (size_t)l * 65536 + (size_t)(r2 & 255) * 256 + c;
        }
        dstbase = (size_t)OFF_KV * 4; n = r; k = c; K = 256;
    } else if (j < OFF_SAWO) {
        int rel = j - OFF_QKV;
        ptr = w_qkv + rel;
        int l = rel / 196608, r = rel % 196608;
        dstbase = ((size_t)OFF_QKV + (size_t)l * 196608) * 4;
        n = r >> 8; k = r & 255; K = 256;
    } else if (j < OFF_CAWQ) {
        int rel = j - OFF_SAWO;
        ptr = w_sawo + rel;
        int l = rel >> 16, r = rel & 65535;
        dstbase = ((size_t)OFF_SAWO + ((size_t)l << 16)) * 4;
        n = r >> 8; k = r & 255; K = 256;
    } else if (j < OFF_KV) {
        int rel = j - OFF_CAWQ;
        ptr = w_caq + rel;
        int l = rel >> 16, r = rel & 65535;
        dstbase = ((size_t)OFF_CAWQ + ((size_t)l << 16)) * 4;
        n = r >> 8; k = r & 255; K = 256;
    } else if (j < OFF_FW1) {
        int rel = j - OFF_CAWO;
        ptr = w_cawo + rel;
        int l = rel >> 16, r = rel & 65535;
        dstbase = ((size_t)OFF_CAWO + ((size_t)l << 16)) * 4;
        n = r >> 8; k = r & 255; K = 256;
    } else if (j < OFF_FW2) {
        int rel = j - OFF_FW1;
        ptr = w_f1 + rel;
        int l = rel / 524288, r = rel % 524288;
        dstbase = ((size_t)OFF_FW1 + (size_t)l * 524288) * 4;
        n = r >> 8; k = r & 255; K = 256;
    } else {
        int rel = j - OFF_FW2;
        ptr = w_f2 + rel;
        int l = rel / 524288, r = rel % 524288;
        dstbase = ((size_t)OFF_FW2 + (size_t)l * 524288) * 4;
        n = r / 2048; k = r % 2048; K = 2048;
    }
    float4 x = *(const float4*)ptr;
    pk_write4(g_wp + dstbase, n, k, K, x);
}

/* ------------------- add + LayerNorm (+ optional packed bf16) ------------------- */
__device__ __forceinline__ float block_sum256(float v, float* red)
{
    #pragma unroll
    for (int o = 16; o; o >>= 1) v += __shfl_xor_sync(0xffffffffu, v, o);
    int w = threadIdx.x >> 5;
    if ((threadIdx.x & 31) == 0) red[w] = v;
    __syncthreads();
    if (threadIdx.x < 32) {
        float u = (threadIdx.x < 8) ? red[threadIdx.x] : 0.f;
        #pragma unroll
        for (int o = 4; o; o >>= 1) u += __shfl_xor_sync(0xffffffffu, u, o);
        if (threadIdx.x == 0) red[0] = u;
    }
    __syncthreads();
    float r = red[0];
    __syncthreads();
    return r;
}

__global__ __launch_bounds__(256) void add_ln_kernel(
    const float* __restrict__ x, const float* __restrict__ y,
    const float* __restrict__ g, const float* __restrict__ b,
    float* __restrict__ out, char* __restrict__ op)
{
    __shared__ float red[8];
    int row = blockIdx.x;
    int tid = threadIdx.x;
    float v = x[(size_t)row * EE + tid];
    if (y) v += y[(size_t)row * EE + tid];
    float mean = block_sum256(v, red) * (1.f / EE);
    float diff = v - mean;
    float var = block_sum256(diff * diff, red) * (1.f / EE);
    float r = diff * rsqrtf(var + 1e-5f) * g[tid] + b[tid];
    out[(size_t)row * EE + tid] = r;
    if (op) {
        __nv_bfloat16 h = __float2bfloat16(r);
        char* d = op + pk_img(row, tid, 256);
        uint32_t off = pk_off(row, tid);
        *(__nv_bfloat16*)(d + SWZ128(off)) = h;
        *(__nv_bfloat16*)(d + SWZ128(off + 64)) =
            __float2bfloat16(r - __bfloat162float(h));
    }
}

/* ------------------------------- host side ------------------------------- */
extern "C" void kernel_launch(void* const* d_in, const int* in_sizes, int n_in,
                              void* d_out, int out_size)
{
    const float* tgt      = (const float*)d_in[0];
    const float* memory   = (const float*)d_in[1];
    const void*  maskraw  = d_in[2];
    const float* sa_wqkv  = (const float*)d_in[3];
    const float* sa_bqkv  = (const float*)d_in[4];
    const float* sa_wo    = (const float*)d_in[5];
    const float* sa_bo    = (const float*)d_in[6];
    const float* ca_wq    = (const float*)d_in[7];
    const float* ca_bq    = (const float*)d_in[8];
    const float* ca_wk    = (const float*)d_in[9];
    const float* ca_bk    = (const float*)d_in[10];
    const float* ca_wv    = (const float*)d_in[11];
    const float* ca_bv    = (const float*)d_in[12];
    const float* ca_wo    = (const float*)d_in[13];
    const float* ca_bo    = (const float*)d_in[14];
    const float* f_w1     = (const float*)d_in[15];
    const float* f_b1     = (const float*)d_in[16];
    const float* f_w2     = (const float*)d_in[17];
    const float* f_b2     = (const float*)d_in[18];
    const float* ln1g     = (const float*)d_in[19];
    const float* ln1b     = (const float*)d_in[20];
    const float* ln2g     = (const float*)d_in[21];
    const float* ln2b     = (const float*)d_in[22];
    const float* ln3g     = (const float*)d_in[23];
    const float* ln3b     = (const float*)d_in[24];
    const float* lnfg     = (const float*)d_in[25];
    const float* lnfb     = (const float*)d_in[26];

    float *t, *sub, *kvbias;
    uint32_t* maskb;
    char *wp, *tp, *ctxp, *memp, *ffp;
    __half *qkvh, *qkvl, *cqh, *cql, *kvh, *kvl;
    cudaGetSymbolAddress((void**)&t,      g_t);
    cudaGetSymbolAddress((void**)&sub,    g_sub);
    cudaGetSymbolAddress((void**)&kvbias, g_kvbias);
    cudaGetSymbolAddress((void**)&maskb,  g_maskbits);
    cudaGetSymbolAddress((void**)&wp,     g_wp);
    cudaGetSymbolAddress((void**)&tp,     g_tp);
    cudaGetSymbolAddress((void**)&ctxp,   g_ctxp);
    cudaGetSymbolAddress((void**)&memp,   g_memp);
    cudaGetSymbolAddress((void**)&ffp,    g_ffp);
    cudaGetSymbolAddress((void**)&qkvh,   g_qkvh);
    cudaGetSymbolAddress((void**)&qkvl,   g_qkvl);
    cudaGetSymbolAddress((void**)&cqh,    g_cqh);
    cudaGetSymbolAddress((void**)&cql,    g_cql);
    cudaGetSymbolAddress((void**)&kvh,    g_kvh);
    cudaGetSymbolAddress((void**)&kvl,    g_kvl);

    const int GSM3 = G_HDR + 3 * GS_STAGE;   /* 2 CTAs/SM */
    const int GSM4 = G_HDR + 4 * GS_STAGE;   /* deep lookahead */
    cudaFuncSetAttribute(gemm_tc<3>, cudaFuncAttributeMaxDynamicSharedMemorySize, GSM3);
    cudaFuncSetAttribute(gemm_tc<4>, cudaFuncAttributeMaxDynamicSharedMemorySize, GSM4);
    cudaFuncSetAttribute(attn_mma, cudaFuncAttributeMaxDynamicSharedMemorySize, ATT_SMEM);

    cudaMemcpyAsync(t, tgt, (size_t)MQ * EE * sizeof(float),
                    cudaMemcpyDeviceToDevice, 0);
    cudaMemcpyAsync(kvbias, ca_bk, 1536 * sizeof(float), cudaMemcpyDeviceToDevice, 0);
    cudaMemcpyAsync(kvbias + 1536, ca_bv, 1536 * sizeof(float), cudaMemcpyDeviceToDevice, 0);

    mask_bits_kernel<<<(MASKW + 255) / 256, 256>>>(maskraw, maskb);
    {
        int tot4 = (MQ * EE + MK * EE) / 4;
        convert_hilo_all<<<(tot4 + 255) / 256, 256>>>(tgt, memory);
    }
    convert_weights<<<(WTOT / 4 + 255) / 256, 256>>>(sa_wqkv, sa_wo, ca_wq, ca_wk,
                                                     ca_wv, ca_wo, f_w1, f_w2);

    /* hoisted: ALL cross-attn K/V projections in one launch */
    gemm_tc<3><<<dim3(24, 256), 256, GSM3>>>(memp, wp + (size_t)OFF_KV * 4, kvbias,
        nullptr, nullptr, kvh, kvl, MK, 3072, 256, 0, 1536, 0);

    dim3 gattn((NQ + 63) / 64, HH, BB);
    dim3 gQKV(6, 19), gSQ(2, 19), gF1(16, 19);

    for (int l = 0; l < LL; l++) {
        /* self-attention */
        gemm_tc<4><<<gQKV, 256, GSM4>>>(tp,
            wp + ((size_t)OFF_QKV + (size_t)l * 196608) * 4,
            sa_bqkv + (size_t)l * 768,
            nullptr, nullptr, qkvh, qkvl, MQ, 768, 256, 0, 768, 0);
        attn_mma<<<gattn, 256, ATT_SMEM>>>(
            qkvh, qkvl, 768, qkvh + 256, qkvl + 256, 768, qkvh + 512, 768,
            nullptr, ctxp, NQ, NQ);
        gemm_tc<4><<<gSQ, 256, GSM4>>>(ctxp,
            wp + ((size_t)OFF_SAWO + ((size_t)l << 16)) * 4,
            sa_bo + (size_t)l * EE,
            sub, nullptr, nullptr, nullptr, MQ, 256, 256, 0, 0, 0);
        add_ln_kernel<<<MQ, 256>>>(t, sub, ln1g + (size_t)l*EE, ln1b + (size_t)l*EE,
                                   t, tp);

        /* cross-attention (K/V precomputed) */
        gemm_tc<4><<<gSQ, 256, GSM4>>>(tp,
            wp + ((size_t)OFF_CAWQ + ((size_t)l << 16)) * 4,
            ca_bq + (size_t)l * EE,
            nullptr, nullptr, cqh, cql, MQ, 256, 256, 0, 256, 0);
        attn_mma<<<gattn, 256, ATT_SMEM>>>(
            cqh, cql, 256,
            kvh + (size_t)l * 256, kvl + (size_t)l * 256, 3072,
            kvh + 1536 + (size_t)l * 256, 3072,
            maskb, ctxp, NQ, NKK);
        gemm_tc<4><<<gSQ, 256, GSM4>>>(ctxp,
            wp + ((size_t)OFF_CAWO + ((size_t)l << 16)) * 4,
            ca_bo + (size_t)l * EE,
            sub, nullptr, nullptr, nullptr, MQ, 256, 256, 0, 0, 0);
        add_ln_kernel<<<MQ, 256>>>(t, sub, ln2g + (size_t)l*EE, ln2b + (size_t)l*EE,
                                   t, tp);

        /* feed-forward */
        gemm_tc<3><<<gF1, 256, GSM3>>>(tp,
            wp + ((size_t)OFF_FW1 + (size_t)l * 524288) * 4,
            f_b1 + (size_t)l * FFDIM,
            nullptr, ffp, nullptr, nullptr, MQ, 2048, 256, 1, 0, 2048);
        gemm_tc<4><<<gSQ, 256, GSM4>>>(ffp,
            wp + ((size_t)OFF_FW2 + (size_t)l * 524288) * 4,
            f_b2 + (size_t)l * EE,
            sub, nullptr, nullptr, nullptr, MQ, 256, 2048, 0, 0, 0);
        add_ln_kernel<<<MQ, 256>>>(t, sub, ln3g + (size_t)l*EE, ln3b + (size_t)l*EE,
                                   t, tp);
    }

    add_ln_kernel<<<MQ, 256>>>(t, nullptr, lnfg, lnfb, (float*)d_out, nullptr);
}

// round 14
// speedup vs baseline: 1.0438x; 1.0438x over previous
#include <cuda_runtime.h>
#include <cuda_bf16.h>
#include <cuda_fp16.h>
#include <math.h>
#include <stdint.h>

#define BB 8
#define NQ 300
#define NKK 4096
#define EE 256
#define HH 8
#define DD 32
#define FFDIM 2048
#define LL 6
#define MQ (BB*NQ)      /* 2400 */
#define MK (BB*NKK)     /* 32768 */
#define MASKN (BB*NQ*NKK)
#define MASKW (MASKN/32)
#define ATT_SCALE 0.17677669529663687f  /* 32^-0.5 */

#if defined(__CUDA_ARCH_FEAT_SM103_ALL) || defined(__CUDA_ARCH_FEAT_SM100_ALL) || \
    (defined(__CUDA_ARCH_SPECIFIC__) && (__CUDA_ARCH_SPECIFIC__ == 1030 || __CUDA_ARCH_SPECIFIC__ == 1000))
#define HAS_TC 1
#else
#define HAS_TC 0
#endif

/* weight bank cumulative offsets (elements).
   [OFF_KV, OFF_CAWO) = combined cross-attn K/V weights:
   3072 rows x 256 = [K_l0..K_l5, V_l0..V_l5]. */
#define OFF_QKV   0
#define OFF_SAWO  1179648
#define OFF_CAWQ  1572864
#define OFF_KV    1966080
#define OFF_CAWO  2752512
#define OFF_FW1   3145728
#define OFF_FW2   6291456
#define WTOT      9437184

#define SWZ128(o) ((o) ^ (((o) >> 3) & 0x70))

/* packed operand layout: 16KB image per (tile128, kchunk32); row = [32 hi | 32 lo] bf16 */
__device__ __host__ __forceinline__ size_t pk_img(int m, int k, int K)
{
    return ((size_t)(m >> 7) * (K >> 5) + (k >> 5)) * 16384;
}
__device__ __host__ __forceinline__ uint32_t pk_off(int m, int k)
{
    return (uint32_t)((m & 127) * 128 + ((k & 31) >> 3) * 16 + (k & 7) * 2);
}

/* ------------ scratch (static device allocations only) ------------ */
__device__ __align__(256) float g_t[MQ*EE];
__device__ __align__(256) float g_sub[MQ*EE];
__device__ __align__(256) float g_kvbias[3072];
__device__ __align__(256) uint32_t g_maskbits[MASKW];
__device__ __align__(256) char g_wp[(size_t)WTOT*4];      /* packed weights (hi+lo) */
__device__ __align__(256) char g_tp[19*8*16384];          /* packed t    (K=256)   */
__device__ __align__(256) char g_ctxp[19*8*16384];        /* packed ctx  (K=256)   */
__device__ __align__(256) char g_memp[(size_t)256*8*16384];/* packed mem (K=256)   */
__device__ __align__(256) char g_ffp[(size_t)19*64*16384]; /* packed ff  (K=2048)  */
__device__ __align__(256) __half g_qkvh[MQ*3*EE], g_qkvl[MQ*3*EE];
__device__ __align__(256) __half g_cqh[MQ*EE], g_cql[MQ*EE];
__device__ __align__(256) __half g_kvh[(size_t)MK*3072];  /* cols [0,1536)=K hi, [1536,3072)=V */
__device__ __align__(256) __half g_kvl[(size_t)MK*3072];  /* K lo */

/* gemm smem layout */
#define GS_STAGE 32768
#define GS_W 16384
#define G_HDR 1024
#define G_IDESC 0x8200490u   /* f32 acc, bf16 a/b, N=128, M=128 */

#if HAS_TC
__device__ __forceinline__ uint32_t smem_u32(const void* p)
{
    uint32_t a;
    asm("{ .reg .u64 t; cvta.to.shared.u64 t, %1; cvt.u32.u64 %0, t; }"
        : "=r"(a) : "l"(p));
    return a;
}

static __device__ __forceinline__ uint64_t make_desc_sw128(uint32_t addr)
{
    const uint64_t base =
        (uint64_t(2)  << 61) | (uint64_t(1) << 46) |
        (uint64_t(64) << 32) | (uint64_t(1) << 16);
    return base | ((uint64_t)(addr >> 4) & 0x3FFF);
}

#define TC_ALLOC(sa, n) \
    asm volatile("tcgen05.alloc.cta_group::1.sync.aligned.shared::cta.b32 [%0], %1;" \
                 :: "r"(sa), "r"((uint32_t)(n)) : "memory")
#define TC_RELINQ() \
    asm volatile("tcgen05.relinquish_alloc_permit.cta_group::1.sync.aligned;")
#define TC_DEALLOC(t, n) \
    asm volatile("tcgen05.dealloc.cta_group::1.sync.aligned.b32 %0, %1;" :: "r"(t), "r"((uint32_t)(n)))
#define TC_COMMIT(mb) \
    asm volatile("tcgen05.commit.cta_group::1.mbarrier::arrive::one.shared::cluster.b64 [%0];" \
                 :: "r"(mb) : "memory")
#define TC_FENCE_AFTER()  asm volatile("tcgen05.fence::after_thread_sync;" ::: "memory")
#define TC_WAIT_LD()      asm volatile("tcgen05.wait::ld.sync.aligned;" ::: "memory")
#define MBAR_INVAL(mb) \
    asm volatile("mbarrier.inval.shared.b64 [%0];" :: "r"(mb) : "memory")
#define MBAR_INIT(mb, cnt) \
    asm volatile("mbarrier.init.shared.b64 [%0], %1;" :: "r"(mb), "r"((uint32_t)(cnt)) : "memory")
#define MBAR_ARRIVE_TX(mb, n) \
    asm volatile("mbarrier.arrive.expect_tx.shared.b64 _, [%0], %1;" \
                 :: "r"(mb), "r"((uint32_t)(n)) : "memory")
#define BULK_G2S(dst, src, n, mb) \
    asm volatile("cp.async.bulk.shared::cluster.global.mbarrier::complete_tx::bytes [%0], [%1], %2, [%3];" \
                 :: "r"(dst), "l"(src), "r"((uint32_t)(n)), "r"(mb) : "memory")
#define MBAR_WAIT(mb, ph) do {                                                   \
    uint32_t _mb = (mb), _ph = (ph), _done;                                      \
    asm volatile(                                                                \
        "{\n\t.reg .pred p;\n\t"                                                 \
        "mbarrier.try_wait.parity.acquire.cta.shared::cta.b64 p, [%1], %2;\n\t"  \
        "selp.b32 %0, 1, 0, p;\n\t}"                                             \
        : "=r"(_done) : "r"(_mb), "r"(_ph) : "memory");                          \
    if (!_done) {                                                                \
        asm volatile(                                                            \
            "{\n\t.reg .pred P1;\n\t"                                            \
            "WL_%=:\n\t"                                                         \
            "mbarrier.try_wait.parity.acquire.cta.shared::cta.b64 P1, [%0], %1, 0x989680;\n\t" \
            "@P1 bra.uni WD_%=;\n\t"                                             \
            "bra.uni WL_%=;\n\t"                                                 \
            "WD_%=:\n\t}"                                                        \
            :: "r"(_mb), "r"(_ph) : "memory");                                   \
    }                                                                            \
} while (0)

__device__ __forceinline__ void tc_mma_f16_ss(
    uint32_t d_tmem, uint64_t a_desc, uint64_t b_desc, uint32_t idesc, uint32_t en)
{
    asm volatile(
        "{\n\t.reg .pred p;\n\t"
        "setp.ne.u32 p, %5, 0;\n\t"
        "tcgen05.mma.cta_group::1.kind::f16 [%0], %1, %2, %3, {%4,%4,%4,%4}, p;\n\t}"
        :: "r"(d_tmem), "l"(a_desc), "l"(b_desc), "r"(idesc), "r"(0u), "r"(en)
        : "memory");
}

#define TC_LD_X32(r, ta) \
    asm volatile( \
        "tcgen05.ld.sync.aligned.32x32b.x32.b32 " \
        "{%0, %1, %2, %3, %4, %5, %6, %7, " \
        " %8, %9, %10, %11, %12, %13, %14, %15, " \
        " %16, %17, %18, %19, %20, %21, %22, %23, " \
        " %24, %25, %26, %27, %28, %29, %30, %31}, [%32];" \
        : "=r"((r)[0]),  "=r"((r)[1]),  "=r"((r)[2]),  "=r"((r)[3]), \
          "=r"((r)[4]),  "=r"((r)[5]),  "=r"((r)[6]),  "=r"((r)[7]), \
          "=r"((r)[8]),  "=r"((r)[9]),  "=r"((r)[10]), "=r"((r)[11]), \
          "=r"((r)[12]), "=r"((r)[13]), "=r"((r)[14]), "=r"((r)[15]), \
          "=r"((r)[16]), "=r"((r)[17]), "=r"((r)[18]), "=r"((r)[19]), \
          "=r"((r)[20]), "=r"((r)[21]), "=r"((r)[22]), "=r"((r)[23]), \
          "=r"((r)[24]), "=r"((r)[25]), "=r"((r)[26]), "=r"((r)[27]), \
          "=r"((r)[28]), "=r"((r)[29]), "=r"((r)[30]), "=r"((r)[31]) \
        : "r"(ta))
#endif /* HAS_TC */

/* ======================= GEMM =======================
   C = A @ W^T + bias with pre-packed bf16 hi/lo operands; hh+hl+lh in fp32 TMEM.
   128x128 CTA tile, K-chunk 32, bulk-copy pipeline driven by ONE thread,
   lookahead STAGES-1.  Outputs: optional f32, packed bf16, f16 hi(/lo). */
template<int STAGES>
__global__ __launch_bounds__(256) void gemm_tc(
    const char* __restrict__ Ap, const char* __restrict__ Wp,
    const float* __restrict__ bias,
    float* __restrict__ Cf, char* __restrict__ Cbp,
    __half* __restrict__ Cfh, __half* __restrict__ Cfl,
    int M, int N, int K, int relu, int lo_ncols, int cbK)
{
#if HAS_TC
    extern __shared__ __align__(1024) char smem[];
    uint32_t sb = smem_u32(smem);
    int tid = threadIdx.x, wid = tid >> 5, lane = tid & 31;
    int mBase = blockIdx.y * 128, nBase = blockIdx.x * 128;
    int nch = K >> 5;
    const int LA = STAGES - 1;   /* prefetch lookahead */

    if (wid == 0) {
        TC_ALLOC(sb, 128);
        TC_RELINQ();   /* same warp, after alloc: no race; frees the SM alloc permit
                          so a co-resident CTA can allocate concurrently */
    }
    __syncthreads();
    uint32_t tmem;
    asm volatile("ld.shared.b32 %0, [%1];" : "=r"(tmem) : "r"(sb));
    if (tid == 0) {
        #pragma unroll
        for (int s = 0; s < STAGES; s++) {
            MBAR_INIT(sb + 8 + s * 8, 1);    /* full[s]    */
            MBAR_INIT(sb + 64 + s * 8, 1);   /* mmaDone[s] */
        }
    }
    __syncthreads();

    if (tid == 0) {
        const char* Abase = Ap + (size_t)blockIdx.y * nch * 16384;
        const char* Wbase = Wp + (size_t)blockIdx.x * nch * 16384;
        #pragma unroll
        for (int p = 0; p < LA; p++) {
            if (p >= nch) break;
            uint32_t st = sb + G_HDR + p * GS_STAGE;
            MBAR_ARRIVE_TX(sb + 8 + p * 8, 32768);
            BULK_G2S(st,        Abase + (size_t)p * 16384, 16384, sb + 8 + p * 8);
            BULK_G2S(st + GS_W, Wbase + (size_t)p * 16384, 16384, sb + 8 + p * 8);
        }
        for (int ch = 0; ch < nch; ch++) {
            int s = ch % STAGES;
            MBAR_WAIT(sb + 8 + s * 8, (uint32_t)((ch / STAGES) & 1));
            uint32_t stb = sb + G_HDR + s * GS_STAGE;
            uint64_t dA = make_desc_sw128(stb);
            uint64_t dW = make_desc_sw128(stb + GS_W);
            #pragma unroll
            for (int ks = 0; ks < 2; ks++) {
                uint64_t o = (uint64_t)(ks * 2);
                tc_mma_f16_ss(tmem, dA + o,     dW + o,     G_IDESC,
                              (ch == 0 && ks == 0) ? 0u : 1u);
                tc_mma_f16_ss(tmem, dA + o,     dW + 4 + o, G_IDESC, 1u);
                tc_mma_f16_ss(tmem, dA + 4 + o, dW + o,     G_IDESC, 1u);
            }
            TC_COMMIT(sb + 64 + s * 8);
            int pre = ch + LA;
            if (pre < nch) {
                int sp = pre % STAGES;
                int tgt = pre - STAGES;
                if (tgt >= 0)
                    MBAR_WAIT(sb + 64 + sp * 8, (uint32_t)((tgt / STAGES) & 1));
                uint32_t stp = sb + G_HDR + sp * GS_STAGE;
                MBAR_ARRIVE_TX(sb + 8 + sp * 8, 32768);
                BULK_G2S(stp,        Abase + (size_t)pre * 16384, 16384, sb + 8 + sp * 8);
                BULK_G2S(stp + GS_W, Wbase + (size_t)pre * 16384, 16384, sb + 8 + sp * 8);
            }
        }
        MBAR_WAIT(sb + 64 + ((nch - 1) % STAGES) * 8,
                  (uint32_t)(((nch - 1) / STAGES) & 1));
    }
    __syncthreads();
    TC_FENCE_AFTER();

    if (wid < 4) {
        int row = mBase + wid * 32 + lane;
        bool rv = row < M;
        #pragma unroll
        for (int cb = 0; cb < 128; cb += 32) {
            uint32_t r[32];
            TC_LD_X32(r, tmem + cb);
            TC_WAIT_LD();
            if (rv) {
                #pragma unroll
                for (int c4 = 0; c4 < 32; c4 += 4) {
                    int col = nBase + cb + c4;
                    float4 bv = *(const float4*)&bias[col];
                    float v0 = __uint_as_float(r[c4+0]) + bv.x;
                    float v1 = __uint_as_float(r[c4+1]) + bv.y;
                    float v2 = __uint_as_float(r[c4+2]) + bv.z;
                    float v3 = __uint_as_float(r[c4+3]) + bv.w;
                    if (relu) {
                        v0 = fmaxf(v0, 0.f); v1 = fmaxf(v1, 0.f);
                        v2 = fmaxf(v2, 0.f); v3 = fmaxf(v3, 0.f);
                    }
                    if (Cf)
                        *(float4*)&Cf[(size_t)row * N + col] = make_float4(v0, v1, v2, v3);
                    if (Cbp) {
                        __nv_bfloat16 h0 = __float2bfloat16(v0);
                        __nv_bfloat16 h1 = __float2bfloat16(v1);
                        __nv_bfloat16 h2 = __float2bfloat16(v2);
                        __nv_bfloat16 h3 = __float2bfloat16(v3);
                        char* d = Cbp + pk_img(row, col, cbK);
                        uint32_t off = pk_off(row, col);
                        uint32_t sh = SWZ128(off), sl = SWZ128(off + 64);
                        *(__nv_bfloat162*)(d + sh)     = __nv_bfloat162(h0, h1);
                        *(__nv_bfloat162*)(d + sh + 4) = __nv_bfloat162(h2, h3);
                        *(__nv_bfloat162*)(d + sl) = __nv_bfloat162(
                            __float2bfloat16(v0 - __bfloat162float(h0)),
                            __float2bfloat16(v1 - __bfloat162float(h1)));
                        *(__nv_bfloat162*)(d + sl + 4) = __nv_bfloat162(
                            __float2bfloat16(v2 - __bfloat162float(h2)),
                            __float2bfloat16(v3 - __bfloat162float(h3)));
                    }
                    if (Cfh) {
                        __half h0 = __float2half_rn(v0), h1 = __float2half_rn(v1);
                        __half h2 = __float2half_rn(v2), h3 = __float2half_rn(v3);
                        *(__half2*)&Cfh[(size_t)row * N + col]     = __half2(h0, h1);
                        *(__half2*)&Cfh[(size_t)row * N + col + 2] = __half2(h2, h3);
                        if (Cfl && col < lo_ncols) {
                            *(__half2*)&Cfl[(size_t)row * N + col] = __half2(
                                __float2half_rn(v0 - __half2float(h0)),
                                __float2half_rn(v1 - __half2float(h1)));
                            *(__half2*)&Cfl[(size_t)row * N + col + 2] = __half2(
                                __float2half_rn(v2 - __half2float(h2)),
                                __float2half_rn(v3 - __half2float(h3)));
                        }
                    }
                }
            }
        }
    }
    __syncthreads();
    if (tid == 0) {
        #pragma unroll
        for (int s = 0; s < STAGES; s++) {
            MBAR_INVAL(sb + 8 + s * 8);
            MBAR_INVAL(sb + 64 + s * 8);
        }
    }
    if (wid == 0) TC_DEALLOC(tmem, 128);
#else
    /* SIMT fallback for the non-accelerated gencode pass (never runs) */
    int tid = threadIdx.x;
    int tx = tid & 15, ty = tid >> 4;
    int row0 = blockIdx.y * 128 + ty * 8, col0 = blockIdx.x * 128 + tx * 8;
    float acc[8][8] = {};
    for (int k = 0; k < K; k++) {
        float a[8], w[8];
        #pragma unroll
        for (int i = 0; i < 8; i++) {
            int m = row0 + i;
            const char* d = Ap + pk_img(m, k, K);
            uint32_t off = pk_off(m, k);
            a[i] = __bfloat162float(*(const __nv_bfloat16*)(d + SWZ128(off))) +
                   __bfloat162float(*(const __nv_bfloat16*)(d + SWZ128(off + 64)));
        }
        #pragma unroll
        for (int j = 0; j < 8; j++) {
            int n = col0 + j;
            const char* d = Wp + pk_img(n, k, K);
            uint32_t off = pk_off(n, k);
            w[j] = __bfloat162float(*(const __nv_bfloat16*)(d + SWZ128(off))) +
                   __bfloat162float(*(const __nv_bfloat16*)(d + SWZ128(off + 64)));
        }
        #pragma unroll
        for (int i = 0; i < 8; i++)
            #pragma unroll
            for (int j = 0; j < 8; j++)
                acc[i][j] += a[i] * w[j];
    }
    #pragma unroll
    for (int i = 0; i < 8; i++) {
        int row = row0 + i;
        if (row >= M) break;
        #pragma unroll
        for (int j = 0; j < 8; j++) {
            int col = col0 + j;
            float v = acc[i][j] + bias[col];
            if (relu) v = fmaxf(v, 0.f);
            if (Cf) Cf[(size_t)row * N + col] = v;
            if (Cbp) {
                __nv_bfloat16 h = __float2bfloat16(v);
                char* d = Cbp + pk_img(row, col, cbK);
                uint32_t off = pk_off(row, col);
                *(__nv_bfloat16*)(d + SWZ128(off)) = h;
                *(__nv_bfloat16*)(d + SWZ128(off + 64)) =
                    __float2bfloat16(v - __bfloat162float(h));
            }
            if (Cfh) {
                __half h = __float2half_rn(v);
                Cfh[(size_t)row * N + col] = h;
                if (Cfl && col < lo_ncols)
                    Cfl[(size_t)row * N + col] = __float2half_rn(v - __half2float(h));
            }
        }
    }
#endif
}

/* ================= tensor-core flash attention (mma.sync fp16) ================= */
#define AT_QH 0
#define AT_QL 5120
#define AT_KH 10240
#define AT_KL 20480
#define AT_P  10240
#define AT_VT 30720
#define AT_S  39424
#define AT_M  73216
#define AT_L  73472
#define AT_AL 73728
#define ATT_SMEM 73984

#define MMA16816(c, a, b0, b1) \
    asm volatile("mma.sync.aligned.m16n8k16.row.col.f32.f16.f16.f32 " \
        "{%0,%1,%2,%3}, {%4,%5,%6,%7}, {%8,%9}, {%0,%1,%2,%3};" \
        : "+f"((c)[0]), "+f"((c)[1]), "+f"((c)[2]), "+f"((c)[3]) \
        : "r"((a)[0]), "r"((a)[1]), "r"((a)[2]), "r"((a)[3]), "r"(b0), "r"(b1))

__global__ __launch_bounds__(256) void attn_mma(
    const __half* __restrict__ qh_g, const __half* __restrict__ ql_g, int qstride,
    const __half* __restrict__ kh_g, const __half* __restrict__ kl_g, int kstride,
    const __half* __restrict__ vh_g, int vstride,
    const uint32_t* __restrict__ maskb,
    char* __restrict__ outp,
    int nq, int nk)
{
    extern __shared__ __align__(16) char sm[];
    __half* Qh = (__half*)(sm + AT_QH);
    __half* Ql = (__half*)(sm + AT_QL);
    __half* Kh = (__half*)(sm + AT_KH);
    __half* Kl = (__half*)(sm + AT_KL);
    __half* P  = (__half*)(sm + AT_P);
    __half* Vt = (__half*)(sm + AT_VT);
    float*  S  = (float*)(sm + AT_S);
    float*  mS = (float*)(sm + AT_M);
    float*  lS = (float*)(sm + AT_L);
    float*  aS = (float*)(sm + AT_AL);

    int tid = threadIdx.x;
    int wid = tid >> 5, lane = tid & 31;
    int gid = lane >> 2, tig = lane & 3;
    int wM = wid & 3, wHalf = wid >> 2;
    int b = blockIdx.z, hd = blockIdx.y;
    int qt = blockIdx.x * 64;

    {
        int row = tid >> 2, d8 = (tid & 3) * 8;
        uint4 vq = make_uint4(0,0,0,0), vl4 = make_uint4(0,0,0,0);
        if (qt + row < nq) {
            size_t base = ((size_t)(b * nq + qt + row)) * qstride + hd * DD + d8;
            vq  = *(const uint4*)&qh_g[base];
            vl4 = *(const uint4*)&ql_g[base];
        }
        *(uint4*)&Qh[row * 40 + d8] = vq;
        *(uint4*)&Ql[row * 40 + d8] = vl4;
    }
    if (tid < 64) { mS[tid] = -INFINITY; lS[tid] = 0.f; }
    __syncthreads();

    uint32_t aQh[2][4], aQl[2][4];
    int ar0 = wM * 16 + gid, ar1 = ar0 + 8;
    #pragma unroll
    for (int ks = 0; ks < 2; ks++) {
        int c0 = ks * 16 + 2 * tig;
        aQh[ks][0] = *(uint32_t*)&Qh[ar0 * 40 + c0];
        aQh[ks][1] = *(uint32_t*)&Qh[ar1 * 40 + c0];
        aQh[ks][2] = *(uint32_t*)&Qh[ar0 * 40 + c0 + 8];
        aQh[ks][3] = *(uint32_t*)&Qh[ar1 * 40 + c0 + 8];
        aQl[ks][0] = *(uint32_t*)&Ql[ar0 * 40 + c0];
        aQl[ks][1] = *(uint32_t*)&Ql[ar1 * 40 + c0];
        aQl[ks][2] = *(uint32_t*)&Ql[ar0 * 40 + c0 + 8];
        aQl[ks][3] = *(uint32_t*)&Ql[ar1 * 40 + c0 + 8];
    }

    float oc[4][4] = {};

    for (int kc = 0; kc < nk; kc += 128) {
        __syncthreads();

        #pragma unroll
        for (int i = 0; i < 2; i++) {
            int idx = tid + i * 256;
            int row = idx >> 2, d8 = (idx & 3) * 8;
            int kg = kc + row;
            uint4 a = make_uint4(0,0,0,0), c4 = make_uint4(0,0,0,0), vv = make_uint4(0,0,0,0);
            if (kg < nk) {
                size_t base = ((size_t)(b * nk + kg)) * kstride + hd * DD + d8;
                a  = *(const uint4*)&kh_g[base];
                c4 = *(const uint4*)&kl_g[base];
                size_t vb = ((size_t)(b * nk + kg)) * vstride + hd * DD + d8;
                vv = *(const uint4*)&vh_g[vb];
            }
            *(uint4*)&Kh[row * 40 + d8] = a;
            *(uint4*)&Kl[row * 40 + d8] = c4;
            const __half* hp = (const __half*)&vv;
            #pragma unroll
            for (int e = 0; e < 8; e++)
                Vt[(d8 + e) * 136 + row] = hp[e];
        }
        __syncthreads();

        #pragma unroll
        for (int nt = 0; nt < 8; nt++) {
            float c[4] = {0.f, 0.f, 0.f, 0.f};
            int bn = wHalf * 64 + nt * 8 + gid;
            #pragma unroll
            for (int ks = 0; ks < 2; ks++) {
                int c0 = ks * 16 + 2 * tig;
                uint32_t bh0 = *(uint32_t*)&Kh[bn * 40 + c0];
                uint32_t bh1 = *(uint32_t*)&Kh[bn * 40 + c0 + 8];
                uint32_t bl0 = *(uint32_t*)&Kl[bn * 40 + c0];
                uint32_t bl1 = *(uint32_t*)&Kl[bn * 40 + c0 + 8];
                MMA16816(c, aQh[ks], bh0, bh1);
                MMA16816(c, aQl[ks], bh0, bh1);
                MMA16816(c, aQh[ks], bl0, bl1);
            }
            int sc = wHalf * 64 + nt * 8 + 2 * tig;
            S[(wM * 16 + gid) * 132 + sc]     = c[0] * ATT_SCALE;
            S[(wM * 16 + gid) * 132 + sc + 1] = c[1] * ATT_SCALE;
            S[(wM * 16 + gid + 8) * 132 + sc]     = c[2] * ATT_SCALE;
            S[(wM * 16 + gid + 8) * 132 + sc + 1] = c[3] * ATT_SCALE;
        }
        __syncthreads();

        {
            int r = tid >> 2, j = tid & 3;
            int qrow = qt + r;
            bool rowValid = qrow < nq;
            uint32_t word = 0xFFFFFFFFu;
            if (!rowValid) word = 0u;
            else if (maskb) word = maskb[(size_t)(b * nq + qrow) * (nk >> 5) + (kc >> 5) + j];
            float mx = -INFINITY;
            #pragma unroll
            for (int e = 0; e < 32; e++) {
                int col = j * 32 + e;
                float s = S[r * 132 + col];
                bool ok = ((word >> e) & 1u) && (kc + col < nk);
                s = ok ? s : -INFINITY;
                S[r * 132 + col] = s;
                mx = fmaxf(mx, s);
            }
            mx = fmaxf(mx, __shfl_xor_sync(0xffffffffu, mx, 1));
            mx = fmaxf(mx, __shfl_xor_sync(0xffffffffu, mx, 2));
            float mOld = mS[r];
            float mNew = fmaxf(mOld, mx);
            float mUse = fmaxf(mNew, -1e30f);
            float psum = 0.f;
            #pragma unroll
            for (int e = 0; e < 32; e++) {
                int col = j * 32 + e;
                float p = __expf(S[r * 132 + col] - mUse);
                P[r * 136 + col] = __float2half_rn(p);
                psum += p;
            }
            psum += __shfl_xor_sync(0xffffffffu, psum, 1);
            psum += __shfl_xor_sync(0xffffffffu, psum, 2);
            if (j == 0) {
                float alpha = __expf(mOld - mUse);
                aS[r] = alpha;
                lS[r] = lS[r] * alpha + psum;
                mS[r] = mNew;
            }
        }
        __syncthreads();

        {
            float f0 = aS[wM * 16 + gid];
            float f1 = aS[wM * 16 + 8 + gid];
            #pragma unroll
            for (int nt = 0; nt < 4; nt++) {
                oc[nt][0] *= f0; oc[nt][1] *= f0;
                oc[nt][2] *= f1; oc[nt][3] *= f1;
            }
            #pragma unroll
            for (int ks = 0; ks < 4; ks++) {
                int kbase = wHalf * 64 + ks * 16;
                uint32_t pa[4];
                pa[0] = *(uint32_t*)&P[(wM * 16 + gid) * 136 + kbase + 2 * tig];
                pa[1] = *(uint32_t*)&P[(wM * 16 + 8 + gid) * 136 + kbase + 2 * tig];
                pa[2] = *(uint32_t*)&P[(wM * 16 + gid) * 136 + kbase + 2 * tig + 8];
                pa[3] = *(uint32_t*)&P[(wM * 16 + 8 + gid) * 136 + kbase + 2 * tig + 8];
                #pragma unroll
                for (int nt = 0; nt < 4; nt++) {
                    uint32_t b0 = *(uint32_t*)&Vt[(nt * 8 + gid) * 136 + kbase + 2 * tig];
                    uint32_t b1 = *(uint32_t*)&Vt[(nt * 8 + gid) * 136 + kbase + 2 * tig + 8];
                    MMA16816(oc[nt], pa, b0, b1);
                }
            }
        }
    }
    __syncthreads();

    float* CB = S;
    if (wHalf == 1) {
        #pragma unroll
        for (int nt = 0; nt < 4; nt++) {
            int cc = nt * 8 + 2 * tig;
            CB[(wM * 16 + gid) * 36 + cc]     = oc[nt][0];
            CB[(wM * 16 + gid) * 36 + cc + 1] = oc[nt][1];
            CB[(wM * 16 + 8 + gid) * 36 + cc]     = oc[nt][2];
            CB[(wM * 16 + 8 + gid) * 36 + cc + 1] = oc[nt][3];
        }
    }
    __syncthreads();
    if (wHalf == 0) {
        int r0 = wM * 16 + gid, r1 = r0 + 8;
        float il0 = 1.f / lS[r0], il1 = 1.f / lS[r1];
        bool v0r = (qt + r0) < nq, v1r = (qt + r1) < nq;
        #pragma unroll
        for (int nt = 0; nt < 4; nt++) {
            int cc = nt * 8 + 2 * tig;
            float x0 = (oc[nt][0] + CB[r0 * 36 + cc]) * il0;
            float x1 = (oc[nt][1] + CB[r0 * 36 + cc + 1]) * il0;
            float x2 = (oc[nt][2] + CB[r1 * 36 + cc]) * il1;
            float x3 = (oc[nt][3] + CB[r1 * 36 + cc + 1]) * il1;
            int col = hd * DD + cc;
            if (v0r) {
                int grow = b * nq + qt + r0;
                __nv_bfloat16 h0 = __float2bfloat16(x0), h1 = __float2bfloat16(x1);
                char* d = outp + pk_img(grow, col, 256);
                uint32_t off = pk_off(grow, col);
                *(__nv_bfloat162*)(d + SWZ128(off)) = __nv_bfloat162(h0, h1);
                *(__nv_bfloat162*)(d + SWZ128(off + 64)) = __nv_bfloat162(
                    __float2bfloat16(x0 - __bfloat162float(h0)),
                    __float2bfloat16(x1 - __bfloat162float(h1)));
            }
            if (v1r) {
                int grow = b * nq + qt + r1;
                __nv_bfloat16 h2 = __float2bfloat16(x2), h3 = __float2bfloat16(x3);
                char* d = outp + pk_img(grow, col, 256);
                uint32_t off = pk_off(grow, col);
                *(__nv_bfloat162*)(d + SWZ128(off)) = __nv_bfloat162(h2, h3);
                *(__nv_bfloat162*)(d + SWZ128(off + 64)) = __nv_bfloat162(
                    __float2bfloat16(x2 - __bfloat162float(h2)),
                    __float2bfloat16(x3 - __bfloat162float(h3)));
            }
        }
    }
}

/* ---------------- setup kernels ---------------- */
__global__ void mask_bits_kernel(const void* __restrict__ raw,
                                 uint32_t* __restrict__ out)
{
    __shared__ int c1, c3;
    int tid = threadIdx.x;
    if (tid == 0) { c1 = 0; c3 = 0; }
    __syncthreads();
    const unsigned char* m = (const unsigned char*)raw;
    if (m[4 * tid + 1]) atomicAdd(&c1, 1);
    if (m[4 * tid + 3]) atomicAdd(&c3, 1);
    __syncthreads();
    int mode = (c1 > 0) ? 0 : ((c3 > 0) ? 2 : 1);

    int w = blockIdx.x * blockDim.x + tid;
    if (w >= MASKW) return;
    size_t base = (size_t)w * 32;
    uint32_t bits = 0;
    if (mode == 0) {
        const unsigned char* p = (const unsigned char*)raw + base;
        #pragma unroll
        for (int e = 0; e < 32; e++) bits |= (uint32_t)(p[e] != 0) << e;
    } else if (mode == 1) {
        const int* p = (const int*)raw + base;
        #pragma unroll
        for (int e = 0; e < 32; e++) bits |= (uint32_t)(p[e] != 0) << e;
    } else {
        const float* p = (const float*)raw + base;
        #pragma unroll
        for (int e = 0; e < 32; e++) bits |= (uint32_t)(p[e] != 0.f) << e;
    }
    out[w] = bits;
}

__device__ __forceinline__ void pk_write4(char* dstbase, int n, int k, int K, float4 x)
{
    __nv_bfloat16 h0 = __float2bfloat16(x.x), h1 = __float2bfloat16(x.y);
    __nv_bfloat16 h2 = __float2bfloat16(x.z), h3 = __float2bfloat16(x.w);
    char* d = dstbase + pk_img(n, k, K);
    uint32_t off = pk_off(n, k);
    uint32_t sh = SWZ128(off), sl = SWZ128(off + 64);
    *(__nv_bfloat162*)(d + sh)     = __nv_bfloat162(h0, h1);
    *(__nv_bfloat162*)(d + sh + 4) = __nv_bfloat162(h2, h3);
    *(__nv_bfloat162*)(d + sl) = __nv_bfloat162(
        __float2bfloat16(x.x - __bfloat162float(h0)),
        __float2bfloat16(x.y - __bfloat162float(h1)));
    *(__nv_bfloat162*)(d + sl + 4) = __nv_bfloat162(
        __float2bfloat16(x.z - __bfloat162float(h2)),
        __float2bfloat16(x.w - __bfloat162float(h3)));
}

__global__ void convert_hilo_all(const float* __restrict__ tgt,
                                 const float* __restrict__ memory)
{
    int i = blockIdx.x * blockDim.x + threadIdx.x;
    int idx = i * 4;
    if (idx < MQ * EE) {
        float4 x = *(const float4*)&tgt[idx];
        pk_write4(g_tp, idx >> 8, idx & 255, 256, x);
    } else if (idx < MQ * EE + MK * EE) {
        int r = idx - MQ * EE;
        float4 x = *(const float4*)&memory[r];
        pk_write4(g_memp, r >> 8, r & 255, 256, x);
    }
}

/* weight packing; [OFF_KV, OFF_CAWO) re-laid-out as 3072 rows = [K_l0..K_l5, V_l0..V_l5] */
__global__ void convert_weights(
    const float* __restrict__ w_qkv, const float* __restrict__ w_sawo,
    const float* __restrict__ w_caq, const float* __restrict__ wk,
    const float* __restrict__ wv,   const float* __restrict__ w_cawo,
    const float* __restrict__ w_f1, const float* __restrict__ w_f2)
{
    int i = blockIdx.x * blockDim.x + threadIdx.x;
    int j = i * 4;
    if (j >= WTOT) return;
    const float* ptr;
    size_t dstbase;
    int n, k, K;
    if (j >= OFF_KV && j < OFF_CAWO) {
        int rel = j - OFF_KV;
        int r = rel >> 8, c = rel & 255;
        if (r < 1536) {
            int l = r >> 8;
            ptr = wk + (size_t)l * 65536 + (size_t)(r & 255) * 256 + c;
        } else {
            int r2 = r - 1536;
            int l = r2 >> 8;
            ptr = wv + (size_t)l * 65536 + (size_t)(r2 & 255) * 256 + c;
        }
        dstbase = (size_t)OFF_KV * 4; n = r; k = c; K = 256;
    } else if (j < OFF_SAWO) {
        int rel = j - OFF_QKV;
        ptr = w_qkv + rel;
        int l = rel / 196608, r = rel % 196608;
        dstbase = ((size_t)OFF_QKV + (size_t)l * 196608) * 4;
        n = r >> 8; k = r & 255; K = 256;
    } else if (j < OFF_CAWQ) {
        int rel = j - OFF_SAWO;
        ptr = w_sawo + rel;
        int l = rel >> 16, r = rel & 65535;
        dstbase = ((size_t)OFF_SAWO + ((size_t)l << 16)) * 4;
        n = r >> 8; k = r & 255; K = 256;
    } else if (j < OFF_KV) {
        int rel = j - OFF_CAWQ;
        ptr = w_caq + rel;
        int l = rel >> 16, r = rel & 65535;
        dstbase = ((size_t)OFF_CAWQ + ((size_t)l << 16)) * 4;
        n = r >> 8; k = r & 255; K = 256;
    } else if (j < OFF_FW1) {
        int rel = j - OFF_CAWO;
        ptr = w_cawo + rel;
        int l = rel >> 16, r = rel & 65535;
        dstbase = ((size_t)OFF_CAWO + ((size_t)l << 16)) * 4;
        n = r >> 8; k = r & 255; K = 256;
    } else if (j < OFF_FW2) {
        int rel = j - OFF_FW1;
        ptr = w_f1 + rel;
        int l = rel / 524288, r = rel % 524288;
        dstbase = ((size_t)OFF_FW1 + (size_t)l * 524288) * 4;
        n = r >> 8; k = r & 255; K = 256;
    } else {
        int rel = j - OFF_FW2;
        ptr = w_f2 + rel;
        int l = rel / 524288, r = rel % 524288;
        dstbase = ((size_t)OFF_FW2 + (size_t)l * 524288) * 4;
        n = r / 2048; k = r % 2048; K = 2048;
    }
    float4 x = *(const float4*)ptr;
    pk_write4(g_wp + dstbase, n, k, K, x);
}

/* ------------------- add + LayerNorm (+ optional packed bf16) ------------------- */
__device__ __forceinline__ float block_sum256(float v, float* red)
{
    #pragma unroll
    for (int o = 16; o; o >>= 1) v += __shfl_xor_sync(0xffffffffu, v, o);
    int w = threadIdx.x >> 5;
    if ((threadIdx.x & 31) == 0) red[w] = v;
    __syncthreads();
    if (threadIdx.x < 32) {
        float u = (threadIdx.x < 8) ? red[threadIdx.x] : 0.f;
        #pragma unroll
        for (int o = 4; o; o >>= 1) u += __shfl_xor_sync(0xffffffffu, u, o);
        if (threadIdx.x == 0) red[0] = u;
    }
    __syncthreads();
    float r = red[0];
    __syncthreads();
    return r;
}

__global__ __launch_bounds__(256) void add_ln_kernel(
    const float* __restrict__ x, const float* __restrict__ y,
    const float* __restrict__ g, const float* __restrict__ b,
    float* __restrict__ out, char* __restrict__ op)
{
    __shared__ float red[8];
    int row = blockIdx.x;
    int tid = threadIdx.x;
    float v = x[(size_t)row * EE + tid];
    if (y) v += y[(size_t)row * EE + tid];
    float mean = block_sum256(v, red) * (1.f / EE);
    float diff = v - mean;
    float var = block_sum256(diff * diff, red) * (1.f / EE);
    float r = diff * rsqrtf(var + 1e-5f) * g[tid] + b[tid];
    out[(size_t)row * EE + tid] = r;
    if (op) {
        __nv_bfloat16 h = __float2bfloat16(r);
        char* d = op + pk_img(row, tid, 256);
        uint32_t off = pk_off(row, tid);
        *(__nv_bfloat16*)(d + SWZ128(off)) = h;
        *(__nv_bfloat16*)(d + SWZ128(off + 64)) =
            __float2bfloat16(r - __bfloat162float(h));
    }
}

/* ------------------------------- host side ------------------------------- */
extern "C" void kernel_launch(void* const* d_in, const int* in_sizes, int n_in,
                              void* d_out, int out_size)
{
    const float* tgt      = (const float*)d_in[0];
    const float* memory   = (const float*)d_in[1];
    const void*  maskraw  = d_in[2];
    const float* sa_wqkv  = (const float*)d_in[3];
    const float* sa_bqkv  = (const float*)d_in[4];
    const float* sa_wo    = (const float*)d_in[5];
    const float* sa_bo    = (const float*)d_in[6];
    const float* ca_wq    = (const float*)d_in[7];
    const float* ca_bq    = (const float*)d_in[8];
    const float* ca_wk    = (const float*)d_in[9];
    const float* ca_bk    = (const float*)d_in[10];
    const float* ca_wv    = (const float*)d_in[11];
    const float* ca_bv    = (const float*)d_in[12];
    const float* ca_wo    = (const float*)d_in[13];
    const float* ca_bo    = (const float*)d_in[14];
    const float* f_w1     = (const float*)d_in[15];
    const float* f_b1     = (const float*)d_in[16];
    const float* f_w2     = (const float*)d_in[17];
    const float* f_b2     = (const float*)d_in[18];
    const float* ln1g     = (const float*)d_in[19];
    const float* ln1b     = (const float*)d_in[20];
    const float* ln2g     = (const float*)d_in[21];
    const float* ln2b     = (const float*)d_in[22];
    const float* ln3g     = (const float*)d_in[23];
    const float* ln3b     = (const float*)d_in[24];
    const float* lnfg     = (const float*)d_in[25];
    const float* lnfb     = (const float*)d_in[26];

    float *t, *sub, *kvbias;
    uint32_t* maskb;
    char *wp, *tp, *ctxp, *memp, *ffp;
    __half *qkvh, *qkvl, *cqh, *cql, *kvh, *kvl;
    cudaGetSymbolAddress((void**)&t,      g_t);
    cudaGetSymbolAddress((void**)&sub,    g_sub);
    cudaGetSymbolAddress((void**)&kvbias, g_kvbias);
    cudaGetSymbolAddress((void**)&maskb,  g_maskbits);
    cudaGetSymbolAddress((void**)&wp,     g_wp);
    cudaGetSymbolAddress((void**)&tp,     g_tp);
    cudaGetSymbolAddress((void**)&ctxp,   g_ctxp);
    cudaGetSymbolAddress((void**)&memp,   g_memp);
    cudaGetSymbolAddress((void**)&ffp,    g_ffp);
    cudaGetSymbolAddress((void**)&qkvh,   g_qkvh);
    cudaGetSymbolAddress((void**)&qkvl,   g_qkvl);
    cudaGetSymbolAddress((void**)&cqh,    g_cqh);
    cudaGetSymbolAddress((void**)&cql,    g_cql);
    cudaGetSymbolAddress((void**)&kvh,    g_kvh);
    cudaGetSymbolAddress((void**)&kvl,    g_kvl);

    const int GSM3 = G_HDR + 3 * GS_STAGE;   /* 99KB -> 2 CTAs/SM (with relinquish) */
    const int GSM4 = G_HDR + 4 * GS_STAGE;   /* deep lookahead for small grids */
    cudaFuncSetAttribute(gemm_tc<3>, cudaFuncAttributeMaxDynamicSharedMemorySize, GSM3);
    cudaFuncSetAttribute(gemm_tc<4>, cudaFuncAttributeMaxDynamicSharedMemorySize, GSM4);
    cudaFuncSetAttribute(attn_mma, cudaFuncAttributeMaxDynamicSharedMemorySize, ATT_SMEM);

    cudaMemcpyAsync(t, tgt, (size_t)MQ * EE * sizeof(float),
                    cudaMemcpyDeviceToDevice, 0);
    cudaMemcpyAsync(kvbias, ca_bk, 1536 * sizeof(float), cudaMemcpyDeviceToDevice, 0);
    cudaMemcpyAsync(kvbias + 1536, ca_bv, 1536 * sizeof(float), cudaMemcpyDeviceToDevice, 0);

    mask_bits_kernel<<<(MASKW + 255) / 256, 256>>>(maskraw, maskb);
    {
        int tot4 = (MQ * EE + MK * EE) / 4;
        convert_hilo_all<<<(tot4 + 255) / 256, 256>>>(tgt, memory);
    }
    convert_weights<<<(WTOT / 4 + 255) / 256, 256>>>(sa_wqkv, sa_wo, ca_wq, ca_wk,
                                                     ca_wv, ca_wo, f_w1, f_w2);

    /* hoisted: ALL cross-attn K/V projections in one launch */
    gemm_tc<3><<<dim3(24, 256), 256, GSM3>>>(memp, wp + (size_t)OFF_KV * 4, kvbias,
        nullptr, nullptr, kvh, kvl, MK, 3072, 256, 0, 1536, 0);

    dim3 gattn((NQ + 63) / 64, HH, BB);
    dim3 gQKV(6, 19), gSQ(2, 19), gF1(16, 19);

    for (int l = 0; l < LL; l++) {
        /* self-attention */
        gemm_tc<4><<<gQKV, 256, GSM4>>>(tp,
            wp + ((size_t)OFF_QKV + (size_t)l * 196608) * 4,
            sa_bqkv + (size_t)l * 768,
            nullptr, nullptr, qkvh, qkvl, MQ, 768, 256, 0, 768, 0);
        attn_mma<<<gattn, 256, ATT_SMEM>>>(
            qkvh, qkvl, 768, qkvh + 256, qkvl + 256, 768, qkvh + 512, 768,
            nullptr, ctxp, NQ, NQ);
        gemm_tc<4><<<gSQ, 256, GSM4>>>(ctxp,
            wp + ((size_t)OFF_SAWO + ((size_t)l << 16)) * 4,
            sa_bo + (size_t)l * EE,
            sub, nullptr, nullptr, nullptr, MQ, 256, 256, 0, 0, 0);
        add_ln_kernel<<<MQ, 256>>>(t, sub, ln1g + (size_t)l*EE, ln1b + (size_t)l*EE,
                                   t, tp);

        /* cross-attention (K/V precomputed) */
        gemm_tc<4><<<gSQ, 256, GSM4>>>(tp,
            wp + ((size_t)OFF_CAWQ + ((size_t)l << 16)) * 4,
            ca_bq + (size_t)l * EE,
            nullptr, nullptr, cqh, cql, MQ, 256, 256, 0, 256, 0);
        attn_mma<<<gattn, 256, ATT_SMEM>>>(
            cqh, cql, 256,
            kvh + (size_t)l * 256, kvl + (size_t)l * 256, 3072,
            kvh + 1536 + (size_t)l * 256, 3072,
            maskb, ctxp, NQ, NKK);
        gemm_tc<4><<<gSQ, 256, GSM4>>>(ctxp,
            wp + ((size_t)OFF_CAWO + ((size_t)l << 16)) * 4,
            ca_bo + (size_t)l * EE,
            sub, nullptr, nullptr, nullptr, MQ, 256, 256, 0, 0, 0);
        add_ln_kernel<<<MQ, 256>>>(t, sub, ln2g + (size_t)l*EE, ln2b + (size_t)l*EE,
                                   t, tp);

        /* feed-forward */
        gemm_tc<3><<<gF1, 256, GSM3>>>(tp,
            wp + ((size_t)OFF_FW1 + (size_t)l * 524288) * 4,
            f_b1 + (size_t)l * FFDIM,
            nullptr, ffp, nullptr, nullptr, MQ, 2048, 256, 1, 0, 2048);
        gemm_tc<4><<<gSQ, 256, GSM4>>>(ffp,
            wp + ((size_t)OFF_FW2 + (size_t)l * 524288) * 4,
            f_b2 + (size_t)l * EE,
            sub, nullptr, nullptr, nullptr, MQ, 256, 2048, 0, 0, 0);
        add_ln_kernel<<<MQ, 256>>>(t, sub, ln3g + (size_t)l*EE, ln3b + (size_t)l*EE,
                                   t, tp);
    }

    add_ln_kernel<<<MQ, 256>>>(t, nullptr, lnfg, lnfb, (float*)d_out, nullptr);
}

// round 16
// speedup vs baseline: 1.0585x; 1.0141x over previous
#include <cuda_runtime.h>
#include <cuda_bf16.h>
#include <cuda_fp16.h>
#include <math.h>
#include <stdint.h>

#define BB 8
#define NQ 300
#define NKK 4096
#define EE 256
#define HH 8
#define DD 32
#define FFDIM 2048
#define LL 6
#define MQ (BB*NQ)      /* 2400 */
#define MK (BB*NKK)     /* 32768 */
#define MASKN (BB*NQ*NKK)
#define MASKW (MASKN/32)
#define ATT_SCALE 0.17677669529663687f  /* 32^-0.5 */

#if defined(__CUDA_ARCH_FEAT_SM103_ALL) || defined(__CUDA_ARCH_FEAT_SM100_ALL) || \
    (defined(__CUDA_ARCH_SPECIFIC__) && (__CUDA_ARCH_SPECIFIC__ == 1030 || __CUDA_ARCH_SPECIFIC__ == 1000))
#define HAS_TC 1
#else
#define HAS_TC 0
#endif

/* weight bank cumulative offsets (elements).
   [OFF_KV, OFF_CAWO) = combined cross-attn K/V weights:
   3072 rows x 256 = [K_l0..K_l5, V_l0..V_l5]. */
#define OFF_QKV   0
#define OFF_SAWO  1179648
#define OFF_CAWQ  1572864
#define OFF_KV    1966080
#define OFF_CAWO  2752512
#define OFF_FW1   3145728
#define OFF_FW2   6291456
#define WTOT      9437184

#define SWZ128(o) ((o) ^ (((o) >> 3) & 0x70))

/* packed operand layout: 16KB image per (tile128, kchunk32); row = [32 hi | 32 lo] bf16 */
__device__ __host__ __forceinline__ size_t pk_img(int m, int k, int K)
{
    return ((size_t)(m >> 7) * (K >> 5) + (k >> 5)) * 16384;
}
__device__ __host__ __forceinline__ uint32_t pk_off(int m, int k)
{
    return (uint32_t)((m & 127) * 128 + ((k & 31) >> 3) * 16 + (k & 7) * 2);
}

/* ------------ scratch (static device allocations only) ------------ */
__device__ __align__(256) float g_t[MQ*EE];
__device__ __align__(256) float g_sub[MQ*EE];
__device__ __align__(256) float g_kvbias[3072];
__device__ __align__(256) uint32_t g_maskbits[MASKW];
__device__ __align__(256) char g_wp[(size_t)WTOT*4];      /* packed weights (hi+lo) */
__device__ __align__(256) char g_tp[19*8*16384];          /* packed t    (K=256)   */
__device__ __align__(256) char g_ctxp[19*8*16384];        /* packed ctx  (K=256)   */
__device__ __align__(256) char g_memp[(size_t)256*8*16384];/* packed mem (K=256)   */
__device__ __align__(256) char g_ffp[(size_t)19*64*16384]; /* packed ff  (K=2048)  */
__device__ __align__(256) __half g_qkvh[MQ*3*EE], g_qkvl[MQ*3*EE];
__device__ __align__(256) __half g_cqh[MQ*EE], g_cql[MQ*EE];
__device__ __align__(256) __half g_kvh[(size_t)MK*3072];  /* cols [0,1536)=K hi, [1536,3072)=V */
__device__ __align__(256) __half g_kvl[(size_t)MK*3072];  /* K lo */

#define G_HDR 1024

#if HAS_TC
__device__ __forceinline__ uint32_t smem_u32(const void* p)
{
    uint32_t a;
    asm("{ .reg .u64 t; cvta.to.shared.u64 t, %1; cvt.u32.u64 %0, t; }"
        : "=r"(a) : "l"(p));
    return a;
}

static __device__ __forceinline__ uint64_t make_desc_sw128(uint32_t addr)
{
    const uint64_t base =
        (uint64_t(2)  << 61) | (uint64_t(1) << 46) |
        (uint64_t(64) << 32) | (uint64_t(1) << 16);
    return base | ((uint64_t)(addr >> 4) & 0x3FFF);
}

#define TC_ALLOC(sa, n) \
    asm volatile("tcgen05.alloc.cta_group::1.sync.aligned.shared::cta.b32 [%0], %1;" \
                 :: "r"(sa), "r"((uint32_t)(n)) : "memory")
#define TC_RELINQ() \
    asm volatile("tcgen05.relinquish_alloc_permit.cta_group::1.sync.aligned;")
#define TC_DEALLOC(t, n) \
    asm volatile("tcgen05.dealloc.cta_group::1.sync.aligned.b32 %0, %1;" :: "r"(t), "r"((uint32_t)(n)))
#define TC_COMMIT(mb) \
    asm volatile("tcgen05.commit.cta_group::1.mbarrier::arrive::one.shared::cluster.b64 [%0];" \
                 :: "r"(mb) : "memory")
#define TC_FENCE_AFTER()  asm volatile("tcgen05.fence::after_thread_sync;" ::: "memory")
#define TC_WAIT_LD()      asm volatile("tcgen05.wait::ld.sync.aligned;" ::: "memory")
#define MBAR_INVAL(mb) \
    asm volatile("mbarrier.inval.shared.b64 [%0];" :: "r"(mb) : "memory")
#define MBAR_INIT(mb, cnt) \
    asm volatile("mbarrier.init.shared.b64 [%0], %1;" :: "r"(mb), "r"((uint32_t)(cnt)) : "memory")
#define MBAR_ARRIVE_TX(mb, n) \
    asm volatile("mbarrier.arrive.expect_tx.shared.b64 _, [%0], %1;" \
                 :: "r"(mb), "r"((uint32_t)(n)) : "memory")
#define BULK_G2S(dst, src, n, mb) \
    asm volatile("cp.async.bulk.shared::cluster.global.mbarrier::complete_tx::bytes [%0], [%1], %2, [%3];" \
                 :: "r"(dst), "l"(src), "r"((uint32_t)(n)), "r"(mb) : "memory")
#define MBAR_WAIT(mb, ph) do {                                                   \
    uint32_t _mb = (mb), _ph = (ph), _done;                                      \
    asm volatile(                                                                \
        "{\n\t.reg .pred p;\n\t"                                                 \
        "mbarrier.try_wait.parity.acquire.cta.shared::cta.b64 p, [%1], %2;\n\t"  \
        "selp.b32 %0, 1, 0, p;\n\t}"                                             \
        : "=r"(_done) : "r"(_mb), "r"(_ph) : "memory");                          \
    if (!_done) {                                                                \
        asm volatile(                                                            \
            "{\n\t.reg .pred P1;\n\t"                                            \
            "WL_%=:\n\t"                                                         \
            "mbarrier.try_wait.parity.acquire.cta.shared::cta.b64 P1, [%0], %1, 0x989680;\n\t" \
            "@P1 bra.uni WD_%=;\n\t"                                             \
            "bra.uni WL_%=;\n\t"                                                 \
            "WD_%=:\n\t}"                                                        \
            :: "r"(_mb), "r"(_ph) : "memory");                                   \
    }                                                                            \
} while (0)

__device__ __forceinline__ void tc_mma_f16_ss(
    uint32_t d_tmem, uint64_t a_desc, uint64_t b_desc, uint32_t idesc, uint32_t en)
{
    asm volatile(
        "{\n\t.reg .pred p;\n\t"
        "setp.ne.u32 p, %5, 0;\n\t"
        "tcgen05.mma.cta_group::1.kind::f16 [%0], %1, %2, %3, {%4,%4,%4,%4}, p;\n\t}"
        :: "r"(d_tmem), "l"(a_desc), "l"(b_desc), "r"(idesc), "r"(0u), "r"(en)
        : "memory");
}

#define TC_LD_X32(r, ta) \
    asm volatile( \
        "tcgen05.ld.sync.aligned.32x32b.x32.b32 " \
        "{%0, %1, %2, %3, %4, %5, %6, %7, " \
        " %8, %9, %10, %11, %12, %13, %14, %15, " \
        " %16, %17, %18, %19, %20, %21, %22, %23, " \
        " %24, %25, %26, %27, %28, %29, %30, %31}, [%32];" \
        : "=r"((r)[0]),  "=r"((r)[1]),  "=r"((r)[2]),  "=r"((r)[3]), \
          "=r"((r)[4]),  "=r"((r)[5]),  "=r"((r)[6]),  "=r"((r)[7]), \
          "=r"((r)[8]),  "=r"((r)[9]),  "=r"((r)[10]), "=r"((r)[11]), \
          "=r"((r)[12]), "=r"((r)[13]), "=r"((r)[14]), "=r"((r)[15]), \
          "=r"((r)[16]), "=r"((r)[17]), "=r"((r)[18]), "=r"((r)[19]), \
          "=r"((r)[20]), "=r"((r)[21]), "=r"((r)[22]), "=r"((r)[23]), \
          "=r"((r)[24]), "=r"((r)[25]), "=r"((r)[26]), "=r"((r)[27]), \
          "=r"((r)[28]), "=r"((r)[29]), "=r"((r)[30]), "=r"((r)[31]) \
        : "r"(ta))
#endif /* HAS_TC */

/* ======================= GEMM =======================
   C = A @ W^T + bias with pre-packed bf16 hi/lo operands; hh+hl+lh in fp32 TMEM.
   128 x NT CTA tile (NT in {64,128}; M stays 128 because M=64 changes the
   tcgen05 TMEM D layout), K-chunk 32, bulk-copy pipeline driven by ONE thread,
   lookahead STAGES-1.  Outputs: optional f32, packed bf16, f16 hi(/lo). */
template<int STAGES, int NT>
__global__ __launch_bounds__(256) void gemm_tc(
    const char* __restrict__ Ap, const char* __restrict__ Wp,
    const float* __restrict__ bias,
    float* __restrict__ Cf, char* __restrict__ Cbp,
    __half* __restrict__ Cfh, __half* __restrict__ Cfl,
    int M, int N, int K, int relu, int lo_ncols, int cbK)
{
#if HAS_TC
    extern __shared__ __align__(1024) char smem[];
    uint32_t sb = smem_u32(smem);
    int tid = threadIdx.x, wid = tid >> 5, lane = tid & 31;
    int mBase = blockIdx.y * 128, nBase = blockIdx.x * NT;
    int nch = K >> 5;
    const int LA = STAGES - 1;
    const int ABYTES = 16384;
    const int WBYTES = NT * 128;
    const int SBYTES = ABYTES + WBYTES;
    const uint32_t IDESC = (1u << 4) | (1u << 7) | (1u << 10) |
                           ((uint32_t)(NT / 8) << 17) | (8u << 24);

    if (wid == 0) {
        TC_ALLOC(sb, NT);
        TC_RELINQ();
    }
    __syncthreads();
    uint32_t tmem;
    asm volatile("ld.shared.b32 %0, [%1];" : "=r"(tmem) : "r"(sb));
    if (tid == 0) {
        #pragma unroll
        for (int s = 0; s < STAGES; s++) {
            MBAR_INIT(sb + 8 + s * 8, 1);    /* full[s]    */
            MBAR_INIT(sb + 64 + s * 8, 1);   /* mmaDone[s] */
        }
    }
    __syncthreads();

    if (tid == 0) {
        const char* Abase = Ap + (size_t)blockIdx.y * nch * 16384;
        const char* Wbase = Wp + (size_t)(nBase >> 7) * nch * 16384
                               + (uint32_t)(nBase & 127) * 128;
        #pragma unroll
        for (int p = 0; p < LA; p++) {
            if (p >= nch) break;
            uint32_t st = sb + G_HDR + p * SBYTES;
            MBAR_ARRIVE_TX(sb + 8 + p * 8, SBYTES);
            BULK_G2S(st,          Abase + (size_t)p * 16384, ABYTES, sb + 8 + p * 8);
            BULK_G2S(st + ABYTES, Wbase + (size_t)p * 16384, WBYTES, sb + 8 + p * 8);
        }
        for (int ch = 0; ch < nch; ch++) {
            int s = ch % STAGES;
            MBAR_WAIT(sb + 8 + s * 8, (uint32_t)((ch / STAGES) & 1));
            uint32_t stb = sb + G_HDR + s * SBYTES;
            uint64_t dA = make_desc_sw128(stb);
            uint64_t dW = make_desc_sw128(stb + ABYTES);
            #pragma unroll
            for (int ks = 0; ks < 2; ks++) {
                uint64_t o = (uint64_t)(ks * 2);
                tc_mma_f16_ss(tmem, dA + o,     dW + o,     IDESC,
                              (ch == 0 && ks == 0) ? 0u : 1u);
                tc_mma_f16_ss(tmem, dA + o,     dW + 4 + o, IDESC, 1u);
                tc_mma_f16_ss(tmem, dA + 4 + o, dW + o,     IDESC, 1u);
            }
            TC_COMMIT(sb + 64 + s * 8);
            int pre = ch + LA;
            if (pre < nch) {
                int sp = pre % STAGES;
                int tgt = pre - STAGES;
                if (tgt >= 0)
                    MBAR_WAIT(sb + 64 + sp * 8, (uint32_t)((tgt / STAGES) & 1));
                uint32_t stp = sb + G_HDR + sp * SBYTES;
                MBAR_ARRIVE_TX(sb + 8 + sp * 8, SBYTES);
                BULK_G2S(stp,          Abase + (size_t)pre * 16384, ABYTES, sb + 8 + sp * 8);
                BULK_G2S(stp + ABYTES, Wbase + (size_t)pre * 16384, WBYTES, sb + 8 + sp * 8);
            }
        }
        MBAR_WAIT(sb + 64 + ((nch - 1) % STAGES) * 8,
                  (uint32_t)(((nch - 1) / STAGES) & 1));
    }
    __syncthreads();
    TC_FENCE_AFTER();

    if (wid < 4) {
        int row = mBase + wid * 32 + lane;
        bool rv = row < M;
        #pragma unroll
        for (int cb = 0; cb < NT; cb += 32) {
            uint32_t r[32];
            TC_LD_X32(r, tmem + cb);
            TC_WAIT_LD();
            if (rv) {
                #pragma unroll
                for (int c4 = 0; c4 < 32; c4 += 4) {
                    int col = nBase + cb + c4;
                    float4 bv = *(const float4*)&bias[col];
                    float v0 = __uint_as_float(r[c4+0]) + bv.x;
                    float v1 = __uint_as_float(r[c4+1]) + bv.y;
                    float v2 = __uint_as_float(r[c4+2]) + bv.z;
                    float v3 = __uint_as_float(r[c4+3]) + bv.w;
                    if (relu) {
                        v0 = fmaxf(v0, 0.f); v1 = fmaxf(v1, 0.f);
                        v2 = fmaxf(v2, 0.f); v3 = fmaxf(v3, 0.f);
                    }
                    if (Cf)
                        *(float4*)&Cf[(size_t)row * N + col] = make_float4(v0, v1, v2, v3);
                    if (Cbp) {
                        __nv_bfloat16 h0 = __float2bfloat16(v0);
                        __nv_bfloat16 h1 = __float2bfloat16(v1);
                        __nv_bfloat16 h2 = __float2bfloat16(v2);
                        __nv_bfloat16 h3 = __float2bfloat16(v3);
                        char* d = Cbp + pk_img(row, col, cbK);
                        uint32_t off = pk_off(row, col);
                        uint32_t sh = SWZ128(off), sl = SWZ128(off + 64);
                        *(__nv_bfloat162*)(d + sh)     = __nv_bfloat162(h0, h1);
                        *(__nv_bfloat162*)(d + sh + 4) = __nv_bfloat162(h2, h3);
                        *(__nv_bfloat162*)(d + sl) = __nv_bfloat162(
                            __float2bfloat16(v0 - __bfloat162float(h0)),
                            __float2bfloat16(v1 - __bfloat162float(h1)));
                        *(__nv_bfloat162*)(d + sl + 4) = __nv_bfloat162(
                            __float2bfloat16(v2 - __bfloat162float(h2)),
                            __float2bfloat16(v3 - __bfloat162float(h3)));
                    }
                    if (Cfh) {
                        __half h0 = __float2half_rn(v0), h1 = __float2half_rn(v1);
                        __half h2 = __float2half_rn(v2), h3 = __float2half_rn(v3);
                        *(__half2*)&Cfh[(size_t)row * N + col]     = __half2(h0, h1);
                        *(__half2*)&Cfh[(size_t)row * N + col + 2] = __half2(h2, h3);
                        if (Cfl && col < lo_ncols) {
                            *(__half2*)&Cfl[(size_t)row * N + col] = __half2(
                                __float2half_rn(v0 - __half2float(h0)),
                                __float2half_rn(v1 - __half2float(h1)));
                            *(__half2*)&Cfl[(size_t)row * N + col + 2] = __half2(
                                __float2half_rn(v2 - __half2float(h2)),
                                __float2half_rn(v3 - __half2float(h3)));
                        }
                    }
                }
            }
        }
    }
    __syncthreads();
    if (tid == 0) {
        #pragma unroll
        for (int s = 0; s < STAGES; s++) {
            MBAR_INVAL(sb + 8 + s * 8);
            MBAR_INVAL(sb + 64 + s * 8);
        }
    }
    if (wid == 0) TC_DEALLOC(tmem, NT);
#else
    /* SIMT fallback for the non-accelerated gencode pass (never runs) */
    int tid = threadIdx.x;
    int mBase = blockIdx.y * 128, nBase = blockIdx.x * NT;
    for (int u = tid; u < 128 * NT; u += 256) {
        int row = mBase + u / NT;
        int col = nBase + u % NT;
        if (row >= M) continue;
        float acc = 0.f;
        for (int k = 0; k < K; k++) {
            const char* da = Ap + pk_img(row, k, K);
            uint32_t oa = pk_off(row, k);
            float a = __bfloat162float(*(const __nv_bfloat16*)(da + SWZ128(oa))) +
                      __bfloat162float(*(const __nv_bfloat16*)(da + SWZ128(oa + 64)));
            const char* dw = Wp + pk_img(col, k, K);
            uint32_t ow = pk_off(col, k);
            float w = __bfloat162float(*(const __nv_bfloat16*)(dw + SWZ128(ow))) +
                      __bfloat162float(*(const __nv_bfloat16*)(dw + SWZ128(ow + 64)));
            acc += a * w;
        }
        float v = acc + bias[col];
        if (relu) v = fmaxf(v, 0.f);
        if (Cf) Cf[(size_t)row * N + col] = v;
        if (Cbp) {
            __nv_bfloat16 h = __float2bfloat16(v);
            char* d = Cbp + pk_img(row, col, cbK);
            uint32_t off = pk_off(row, col);
            *(__nv_bfloat16*)(d + SWZ128(off)) = h;
            *(__nv_bfloat16*)(d + SWZ128(off + 64)) =
                __float2bfloat16(v - __bfloat162float(h));
        }
        if (Cfh) {
            __half h = __float2half_rn(v);
            Cfh[(size_t)row * N + col] = h;
            if (Cfl && col < lo_ncols)
                Cfl[(size_t)row * N + col] = __float2half_rn(v - __half2float(h));
        }
    }
#endif
}

/* ================= tensor-core flash attention (mma.sync fp16) ================= */
#define AT_QH 0
#define AT_QL 5120
#define AT_KH 10240
#define AT_KL 20480
#define AT_P  10240
#define AT_VT 30720
#define AT_S  39424
#define AT_M  73216
#define AT_L  73472
#define AT_AL 73728
#define ATT_SMEM 73984

#define MMA16816(c, a, b0, b1) \
    asm volatile("mma.sync.aligned.m16n8k16.row.col.f32.f16.f16.f32 " \
        "{%0,%1,%2,%3}, {%4,%5,%6,%7}, {%8,%9}, {%0,%1,%2,%3};" \
        : "+f"((c)[0]), "+f"((c)[1]), "+f"((c)[2]), "+f"((c)[3]) \
        : "r"((a)[0]), "r"((a)[1]), "r"((a)[2]), "r"((a)[3]), "r"(b0), "r"(b1))

__global__ __launch_bounds__(256) void attn_mma(
    const __half* __restrict__ qh_g, const __half* __restrict__ ql_g, int qstride,
    const __half* __restrict__ kh_g, const __half* __restrict__ kl_g, int kstride,
    const __half* __restrict__ vh_g, int vstride,
    const uint32_t* __restrict__ maskb,
    char* __restrict__ outp,
    int nq, int nk)
{
    extern __shared__ __align__(16) char sm[];
    __half* Qh = (__half*)(sm + AT_QH);
    __half* Ql = (__half*)(sm + AT_QL);
    __half* Kh = (__half*)(sm + AT_KH);
    __half* Kl = (__half*)(sm + AT_KL);
    __half* P  = (__half*)(sm + AT_P);
    __half* Vt = (__half*)(sm + AT_VT);
    float*  S  = (float*)(sm + AT_S);
    float*  mS = (float*)(sm + AT_M);
    float*  lS = (float*)(sm + AT_L);
    float*  aS = (float*)(sm + AT_AL);

    int tid = threadIdx.x;
    int wid = tid >> 5, lane = tid & 31;
    int gid = lane >> 2, tig = lane & 3;
    int wM = wid & 3, wHalf = wid >> 2;
    int b = blockIdx.z, hd = blockIdx.y;
    int qt = blockIdx.x * 64;

    {
        int row = tid >> 2, d8 = (tid & 3) * 8;
        uint4 vq = make_uint4(0,0,0,0), vl4 = make_uint4(0,0,0,0);
        if (qt + row < nq) {
            size_t base = ((size_t)(b * nq + qt + row)) * qstride + hd * DD + d8;
            vq  = *(const uint4*)&qh_g[base];
            vl4 = *(const uint4*)&ql_g[base];
        }
        *(uint4*)&Qh[row * 40 + d8] = vq;
        *(uint4*)&Ql[row * 40 + d8] = vl4;
    }
    if (tid < 64) { mS[tid] = -INFINITY; lS[tid] = 0.f; }
    __syncthreads();

    uint32_t aQh[2][4], aQl[2][4];
    int ar0 = wM * 16 + gid, ar1 = ar0 + 8;
    #pragma unroll
    for (int ks = 0; ks < 2; ks++) {
        int c0 = ks * 16 + 2 * tig;
        aQh[ks][0] = *(uint32_t*)&Qh[ar0 * 40 + c0];
        aQh[ks][1] = *(uint32_t*)&Qh[ar1 * 40 + c0];
        aQh[ks][2] = *(uint32_t*)&Qh[ar0 * 40 + c0 + 8];
        aQh[ks][3] = *(uint32_t*)&Qh[ar1 * 40 + c0 + 8];
        aQl[ks][0] = *(uint32_t*)&Ql[ar0 * 40 + c0];
        aQl[ks][1] = *(uint32_t*)&Ql[ar1 * 40 + c0];
        aQl[ks][2] = *(uint32_t*)&Ql[ar0 * 40 + c0 + 8];
        aQl[ks][3] = *(uint32_t*)&Ql[ar1 * 40 + c0 + 8];
    }

    float oc[4][4] = {};

    for (int kc = 0; kc < nk; kc += 128) {
        __syncthreads();

        #pragma unroll
        for (int i = 0; i < 2; i++) {
            int idx = tid + i * 256;
            int row = idx >> 2, d8 = (idx & 3) * 8;
            int kg = kc + row;
            uint4 a = make_uint4(0,0,0,0), c4 = make_uint4(0,0,0,0), vv = make_uint4(0,0,0,0);
            if (kg < nk) {
                size_t base = ((size_t)(b * nk + kg)) * kstride + hd * DD + d8;
                a  = *(const uint4*)&kh_g[base];
                c4 = *(const uint4*)&kl_g[base];
                size_t vb = ((size_t)(b * nk + kg)) * vstride + hd * DD + d8;
                vv = *(const uint4*)&vh_g[vb];
            }
            *(uint4*)&Kh[row * 40 + d8] = a;
            *(uint4*)&Kl[row * 40 + d8] = c4;
            const __half* hp = (const __half*)&vv;
            #pragma unroll
            for (int e = 0; e < 8; e++)
                Vt[(d8 + e) * 136 + row] = hp[e];
        }
        __syncthreads();

        #pragma unroll
        for (int nt = 0; nt < 8; nt++) {
            float c[4] = {0.f, 0.f, 0.f, 0.f};
            int bn = wHalf * 64 + nt * 8 + gid;
            #pragma unroll
            for (int ks = 0; ks < 2; ks++) {
                int c0 = ks * 16 + 2 * tig;
                uint32_t bh0 = *(uint32_t*)&Kh[bn * 40 + c0];
                uint32_t bh1 = *(uint32_t*)&Kh[bn * 40 + c0 + 8];
                uint32_t bl0 = *(uint32_t*)&Kl[bn * 40 + c0];
                uint32_t bl1 = *(uint32_t*)&Kl[bn * 40 + c0 + 8];
                MMA16816(c, aQh[ks], bh0, bh1);
                MMA16816(c, aQl[ks], bh0, bh1);
                MMA16816(c, aQh[ks], bl0, bl1);
            }
            int sc = wHalf * 64 + nt * 8 + 2 * tig;
            S[(wM * 16 + gid) * 132 + sc]     = c[0] * ATT_SCALE;
            S[(wM * 16 + gid) * 132 + sc + 1] = c[1] * ATT_SCALE;
            S[(wM * 16 + gid + 8) * 132 + sc]     = c[2] * ATT_SCALE;
            S[(wM * 16 + gid + 8) * 132 + sc + 1] = c[3] * ATT_SCALE;
        }
        __syncthreads();

        {
            int r = tid >> 2, j = tid & 3;
            int qrow = qt + r;
            bool rowValid = qrow < nq;
            uint32_t word = 0xFFFFFFFFu;
            if (!rowValid) word = 0u;
            else if (maskb) word = maskb[(size_t)(b * nq + qrow) * (nk >> 5) + (kc >> 5) + j];
            float mx = -INFINITY;
            #pragma unroll
            for (int e = 0; e < 32; e++) {
                int col = j * 32 + e;
                float s = S[r * 132 + col];
                bool ok = ((word >> e) & 1u) && (kc + col < nk);
                s = ok ? s : -INFINITY;
                S[r * 132 + col] = s;
                mx = fmaxf(mx, s);
            }
            mx = fmaxf(mx, __shfl_xor_sync(0xffffffffu, mx, 1));
            mx = fmaxf(mx, __shfl_xor_sync(0xffffffffu, mx, 2));
            float mOld = mS[r];
            float mNew = fmaxf(mOld, mx);
            float mUse = fmaxf(mNew, -1e30f);
            float psum = 0.f;
            #pragma unroll
            for (int e = 0; e < 32; e++) {
                int col = j * 32 + e;
                float p = __expf(S[r * 132 + col] - mUse);
                P[r * 136 + col] = __float2half_rn(p);
                psum += p;
            }
            psum += __shfl_xor_sync(0xffffffffu, psum, 1);
            psum += __shfl_xor_sync(0xffffffffu, psum, 2);
            if (j == 0) {
                float alpha = __expf(mOld - mUse);
                aS[r] = alpha;
                lS[r] = lS[r] * alpha + psum;
                mS[r] = mNew;
            }
        }
        __syncthreads();

        {
            float f0 = aS[wM * 16 + gid];
            float f1 = aS[wM * 16 + 8 + gid];
            #pragma unroll
            for (int nt = 0; nt < 4; nt++) {
                oc[nt][0] *= f0; oc[nt][1] *= f0;
                oc[nt][2] *= f1; oc[nt][3] *= f1;
            }
            #pragma unroll
            for (int ks = 0; ks < 4; ks++) {
                int kbase = wHalf * 64 + ks * 16;
                uint32_t pa[4];
                pa[0] = *(uint32_t*)&P[(wM * 16 + gid) * 136 + kbase + 2 * tig];
                pa[1] = *(uint32_t*)&P[(wM * 16 + 8 + gid) * 136 + kbase + 2 * tig];
                pa[2] = *(uint32_t*)&P[(wM * 16 + gid) * 136 + kbase + 2 * tig + 8];
                pa[3] = *(uint32_t*)&P[(wM * 16 + 8 + gid) * 136 + kbase + 2 * tig + 8];
                #pragma unroll
                for (int nt = 0; nt < 4; nt++) {
                    uint32_t b0 = *(uint32_t*)&Vt[(nt * 8 + gid) * 136 + kbase + 2 * tig];
                    uint32_t b1 = *(uint32_t*)&Vt[(nt * 8 + gid) * 136 + kbase + 2 * tig + 8];
                    MMA16816(oc[nt], pa, b0, b1);
                }
            }
        }
    }
    __syncthreads();

    float* CB = S;
    if (wHalf == 1) {
        #pragma unroll
        for (int nt = 0; nt < 4; nt++) {
            int cc = nt * 8 + 2 * tig;
            CB[(wM * 16 + gid) * 36 + cc]     = oc[nt][0];
            CB[(wM * 16 + gid) * 36 + cc + 1] = oc[nt][1];
            CB[(wM * 16 + 8 + gid) * 36 + cc]     = oc[nt][2];
            CB[(wM * 16 + 8 + gid) * 36 + cc + 1] = oc[nt][3];
        }
    }
    __syncthreads();
    if (wHalf == 0) {
        int r0 = wM * 16 + gid, r1 = r0 + 8;
        float il0 = 1.f / lS[r0], il1 = 1.f / lS[r1];
        bool v0r = (qt + r0) < nq, v1r = (qt + r1) < nq;
        #pragma unroll
        for (int nt = 0; nt < 4; nt++) {
            int cc = nt * 8 + 2 * tig;
            float x0 = (oc[nt][0] + CB[r0 * 36 + cc]) * il0;
            float x1 = (oc[nt][1] + CB[r0 * 36 + cc + 1]) * il0;
            float x2 = (oc[nt][2] + CB[r1 * 36 + cc]) * il1;
            float x3 = (oc[nt][3] + CB[r1 * 36 + cc + 1]) * il1;
            int col = hd * DD + cc;
            if (v0r) {
                int grow = b * nq + qt + r0;
                __nv_bfloat16 h0 = __float2bfloat16(x0), h1 = __float2bfloat16(x1);
                char* d = outp + pk_img(grow, col, 256);
                uint32_t off = pk_off(grow, col);
                *(__nv_bfloat162*)(d + SWZ128(off)) = __nv_bfloat162(h0, h1);
                *(__nv_bfloat162*)(d + SWZ128(off + 64)) = __nv_bfloat162(
                    __float2bfloat16(x0 - __bfloat162float(h0)),
                    __float2bfloat16(x1 - __bfloat162float(h1)));
            }
            if (v1r) {
                int grow = b * nq + qt + r1;
                __nv_bfloat16 h2 = __float2bfloat16(x2), h3 = __float2bfloat16(x3);
                char* d = outp + pk_img(grow, col, 256);
                uint32_t off = pk_off(grow, col);
                *(__nv_bfloat162*)(d + SWZ128(off)) = __nv_bfloat162(h2, h3);
                *(__nv_bfloat162*)(d + SWZ128(off + 64)) = __nv_bfloat162(
                    __float2bfloat16(x2 - __bfloat162float(h2)),
                    __float2bfloat16(x3 - __bfloat162float(h3)));
            }
        }
    }
}

/* ---------------- setup kernels ---------------- */
__global__ void mask_bits_kernel(const void* __restrict__ raw,
                                 uint32_t* __restrict__ out)
{
    __shared__ int c1, c3;
    int tid = threadIdx.x;
    if (tid == 0) { c1 = 0; c3 = 0; }
    __syncthreads();
    const unsigned char* m = (const unsigned char*)raw;
    if (m[4 * tid + 1]) atomicAdd(&c1, 1);
    if (m[4 * tid + 3]) atomicAdd(&c3, 1);
    __syncthreads();
    int mode = (c1 > 0) ? 0 : ((c3 > 0) ? 2 : 1);

    int w = blockIdx.x * blockDim.x + tid;
    if (w >= MASKW) return;
    size_t base = (size_t)w * 32;
    uint32_t bits = 0;
    if (mode == 0) {
        const unsigned char* p = (const unsigned char*)raw + base;
        #pragma unroll
        for (int e = 0; e < 32; e++) bits |= (uint32_t)(p[e] != 0) << e;
    } else if (mode == 1) {
        const int* p = (const int*)raw + base;
        #pragma unroll
        for (int e = 0; e < 32; e++) bits |= (uint32_t)(p[e] != 0) << e;
    } else {
        const float* p = (const float*)raw + base;
        #pragma unroll
        for (int e = 0; e < 32; e++) bits |= (uint32_t)(p[e] != 0.f) << e;
    }
    out[w] = bits;
}

__device__ __forceinline__ void pk_write4(char* dstbase, int n, int k, int K, float4 x)
{
    __nv_bfloat16 h0 = __float2bfloat16(x.x), h1 = __float2bfloat16(x.y);
    __nv_bfloat16 h2 = __float2bfloat16(x.z), h3 = __float2bfloat16(x.w);
    char* d = dstbase + pk_img(n, k, K);
    uint32_t off = pk_off(n, k);
    uint32_t sh = SWZ128(off), sl = SWZ128(off + 64);
    *(__nv_bfloat162*)(d + sh)     = __nv_bfloat162(h0, h1);
    *(__nv_bfloat162*)(d + sh + 4) = __nv_bfloat162(h2, h3);
    *(__nv_bfloat162*)(d + sl) = __nv_bfloat162(
        __float2bfloat16(x.x - __bfloat162float(h0)),
        __float2bfloat16(x.y - __bfloat162float(h1)));
    *(__nv_bfloat162*)(d + sl + 4) = __nv_bfloat162(
        __float2bfloat16(x.z - __bfloat162float(h2)),
        __float2bfloat16(x.w - __bfloat162float(h3)));
}

__global__ void convert_hilo_all(const float* __restrict__ tgt,
                                 const float* __restrict__ memory)
{
    int i = blockIdx.x * blockDim.x + threadIdx.x;
    int idx = i * 4;
    if (idx < MQ * EE) {
        float4 x = *(const float4*)&tgt[idx];
        pk_write4(g_tp, idx >> 8, idx & 255, 256, x);
    } else if (idx < MQ * EE + MK * EE) {
        int r = idx - MQ * EE;
        float4 x = *(const float4*)&memory[r];
        pk_write4(g_memp, r >> 8, r & 255, 256, x);
    }
}

/* weight packing; [OFF_KV, OFF_CAWO) re-laid-out as 3072 rows = [K_l0..K_l5, V_l0..V_l5] */
__global__ void convert_weights(
    const float* __restrict__ w_qkv, const float* __restrict__ w_sawo,
    const float* __restrict__ w_caq, const float* __restrict__ wk,
    const float* __restrict__ wv,   const float* __restrict__ w_cawo,
    const float* __restrict__ w_f1, const float* __restrict__ w_f2)
{
    int i = blockIdx.x * blockDim.x + threadIdx.x;
    int j = i * 4;
    if (j >= WTOT) return;
    const float* ptr;
    size_t dstbase;
    int n, k, K;
    if (j >= OFF_KV && j < OFF_CAWO) {
        int rel = j - OFF_KV;
        int r = rel >> 8, c = rel & 255;
        if (r < 1536) {
            int l = r >> 8;
            ptr = wk + (size_t)l * 65536 + (size_t)(r & 255) * 256 + c;
        } else {
            int r2 = r - 1536;
            int l = r2 >> 8;
            ptr = wv + (size_t)l * 65536 + (size_t)(r2 & 255) * 256 + c;
        }
        dstbase = (size_t)OFF_KV * 4; n = r; k = c; K = 256;
    } else if (j < OFF_SAWO) {
        int rel = j - OFF_QKV;
        ptr = w_qkv + rel;
        int l = rel / 196608, r = rel % 196608;
        dstbase = ((size_t)OFF_QKV + (size_t)l * 196608) * 4;
        n = r >> 8; k = r & 255; K = 256;
    } else if (j < OFF_CAWQ) {
        int rel = j - OFF_SAWO;
        ptr = w_sawo + rel;
        int l = rel >> 16, r = rel & 65535;
        dstbase = ((size_t)OFF_SAWO + ((size_t)l << 16)) * 4;
        n = r >> 8; k = r & 255; K = 256;
    } else if (j < OFF_KV) {
        int rel = j - OFF_CAWQ;
        ptr = w_caq + rel;
        int l = rel >> 16, r = rel & 65535;
        dstbase = ((size_t)OFF_CAWQ + ((size_t)l << 16)) * 4;
        n = r >> 8; k = r & 255; K = 256;
    } else if (j < OFF_FW1) {
        int rel = j - OFF_CAWO;
        ptr = w_cawo + rel;
        int l = rel >> 16, r = rel & 65535;
        dstbase = ((size_t)OFF_CAWO + ((size_t)l << 16)) * 4;
        n = r >> 8; k = r & 255; K = 256;
    } else if (j < OFF_FW2) {
        int rel = j - OFF_FW1;
        ptr = w_f1 + rel;
        int l = rel / 524288, r = rel % 524288;
        dstbase = ((size_t)OFF_FW1 + (size_t)l * 524288) * 4;
        n = r >> 8; k = r & 255; K = 256;
    } else {
        int rel = j - OFF_FW2;
        ptr = w_f2 + rel;
        int l = rel / 524288, r = rel % 524288;
        dstbase = ((size_t)OFF_FW2 + (size_t)l * 524288) * 4;
        n = r / 2048; k = r % 2048; K = 2048;
    }
    float4 x = *(const float4*)ptr;
    pk_write4(g_wp + dstbase, n, k, K, x);
}

/* ------------------- add + LayerNorm (+ optional packed bf16) ------------------- */
__device__ __forceinline__ float block_sum256(float v, float* red)
{
    #pragma unroll
    for (int o = 16; o; o >>= 1) v += __shfl_xor_sync(0xffffffffu, v, o);
    int w = threadIdx.x >> 5;
    if ((threadIdx.x & 31) == 0) red[w] = v;
    __syncthreads();
    if (threadIdx.x < 32) {
        float u = (threadIdx.x < 8) ? red[threadIdx.x] : 0.f;
        #pragma unroll
        for (int o = 4; o; o >>= 1) u += __shfl_xor_sync(0xffffffffu, u, o);
        if (threadIdx.x == 0) red[0] = u;
    }
    __syncthreads();
    float r = red[0];
    __syncthreads();
    return r;
}

__global__ __launch_bounds__(256) void add_ln_kernel(
    const float* __restrict__ x, const float* __restrict__ y,
    const float* __restrict__ g, const float* __restrict__ b,
    float* __restrict__ out, char* __restrict__ op)
{
    __shared__ float red[8];
    int row = blockIdx.x;
    int tid = threadIdx.x;
    float v = x[(size_t)row * EE + tid];
    if (y) v += y[(size_t)row * EE + tid];
    float mean = block_sum256(v, red) * (1.f / EE);
    float diff = v - mean;
    float var = block_sum256(diff * diff, red) * (1.f / EE);
    float r = diff * rsqrtf(var + 1e-5f) * g[tid] + b[tid];
    out[(size_t)row * EE + tid] = r;
    if (op) {
        __nv_bfloat16 h = __float2bfloat16(r);
        char* d = op + pk_img(row, tid, 256);
        uint32_t off = pk_off(row, tid);
        *(__nv_bfloat16*)(d + SWZ128(off)) = h;
        *(__nv_bfloat16*)(d + SWZ128(off + 64)) =
            __float2bfloat16(r - __bfloat162float(h));
    }
}

/* ------------------------------- host side ------------------------------- */
extern "C" void kernel_launch(void* const* d_in, const int* in_sizes, int n_in,
                              void* d_out, int out_size)
{
    const float* tgt      = (const float*)d_in[0];
    const float* memory   = (const float*)d_in[1];
    const void*  maskraw  = d_in[2];
    const float* sa_wqkv  = (const float*)d_in[3];
    const float* sa_bqkv  = (const float*)d_in[4];
    const float* sa_wo    = (const float*)d_in[5];
    const float* sa_bo    = (const float*)d_in[6];
    const float* ca_wq    = (const float*)d_in[7];
    const float* ca_bq    = (const float*)d_in[8];
    const float* ca_wk    = (const float*)d_in[9];
    const float* ca_bk    = (const float*)d_in[10];
    const float* ca_wv    = (const float*)d_in[11];
    const float* ca_bv    = (const float*)d_in[12];
    const float* ca_wo    = (const float*)d_in[13];
    const float* ca_bo    = (const float*)d_in[14];
    const float* f_w1     = (const float*)d_in[15];
    const float* f_b1     = (const float*)d_in[16];
    const float* f_w2     = (const float*)d_in[17];
    const float* f_b2     = (const float*)d_in[18];
    const float* ln1g     = (const float*)d_in[19];
    const float* ln1b     = (const float*)d_in[20];
    const float* ln2g     = (const float*)d_in[21];
    const float* ln2b     = (const float*)d_in[22];
    const float* ln3g     = (const float*)d_in[23];
    const float* ln3b     = (const float*)d_in[24];
    const float* lnfg     = (const float*)d_in[25];
    const float* lnfb     = (const float*)d_in[26];

    float *t, *sub, *kvbias;
    uint32_t* maskb;
    char *wp, *tp, *ctxp, *memp, *ffp;
    __half *qkvh, *qkvl, *cqh, *cql, *kvh, *kvl;
    cudaGetSymbolAddress((void**)&t,      g_t);
    cudaGetSymbolAddress((void**)&sub,    g_sub);
    cudaGetSymbolAddress((void**)&kvbias, g_kvbias);
    cudaGetSymbolAddress((void**)&maskb,  g_maskbits);
    cudaGetSymbolAddress((void**)&wp,     g_wp);
    cudaGetSymbolAddress((void**)&tp,     g_tp);
    cudaGetSymbolAddress((void**)&ctxp,   g_ctxp);
    cudaGetSymbolAddress((void**)&memp,   g_memp);
    cudaGetSymbolAddress((void**)&ffp,    g_ffp);
    cudaGetSymbolAddress((void**)&qkvh,   g_qkvh);
    cudaGetSymbolAddress((void**)&qkvl,   g_qkvl);
    cudaGetSymbolAddress((void**)&cqh,    g_cqh);
    cudaGetSymbolAddress((void**)&cql,    g_cql);
    cudaGetSymbolAddress((void**)&kvh,    g_kvh);
    cudaGetSymbolAddress((void**)&kvl,    g_kvl);

    const int GSM3_128 = G_HDR + 3 * 32768;   /* 99KB: 2 CTAs/SM */
    const int GSM4_128 = G_HDR + 4 * 32768;   /* 132KB: deep lookahead */
    const int GSM4_64  = G_HDR + 4 * 24576;   /* 99KB: 2 CTAs/SM, NT=64 */
    cudaFuncSetAttribute((gemm_tc<3,128>), cudaFuncAttributeMaxDynamicSharedMemorySize, GSM3_128);
    cudaFuncSetAttribute((gemm_tc<4,128>), cudaFuncAttributeMaxDynamicSharedMemorySize, GSM4_128);
    cudaFuncSetAttribute((gemm_tc<4,64>),  cudaFuncAttributeMaxDynamicSharedMemorySize, GSM4_64);
    cudaFuncSetAttribute(attn_mma, cudaFuncAttributeMaxDynamicSharedMemorySize, ATT_SMEM);

    cudaMemcpyAsync(t, tgt, (size_t)MQ * EE * sizeof(float),
                    cudaMemcpyDeviceToDevice, 0);
    cudaMemcpyAsync(kvbias, ca_bk, 1536 * sizeof(float), cudaMemcpyDeviceToDevice, 0);
    cudaMemcpyAsync(kvbias + 1536, ca_bv, 1536 * sizeof(float), cudaMemcpyDeviceToDevice, 0);

    mask_bits_kernel<<<(MASKW + 255) / 256, 256>>>(maskraw, maskb);
    {
        int tot4 = (MQ * EE + MK * EE) / 4;
        convert_hilo_all<<<(tot4 + 255) / 256, 256>>>(tgt, memory);
    }
    convert_weights<<<(WTOT / 4 + 255) / 256, 256>>>(sa_wqkv, sa_wo, ca_wq, ca_wk,
                                                     ca_wv, ca_wo, f_w1, f_w2);

    /* hoisted: ALL cross-attn K/V projections in one launch */
    gemm_tc<3,128><<<dim3(24, 256), 256, GSM3_128>>>(memp, wp + (size_t)OFF_KV * 4, kvbias,
        nullptr, nullptr, kvh, kvl, MK, 3072, 256, 0, 1536, 0);

    dim3 gattn((NQ + 63) / 64, HH, BB);
    dim3 gQKV(6, 19), gSQ64(4, 19), gF1(16, 19);

    for (int l = 0; l < LL; l++) {
        /* self-attention */
        gemm_tc<4,128><<<gQKV, 256, GSM4_128>>>(tp,
            wp + ((size_t)OFF_QKV + (size_t)l * 196608) * 4,
            sa_bqkv + (size_t)l * 768,
            nullptr, nullptr, qkvh, qkvl, MQ, 768, 256, 0, 768, 0);
        attn_mma<<<gattn, 256, ATT_SMEM>>>(
            qkvh, qkvl, 768, qkvh + 256, qkvl + 256, 768, qkvh + 512, 768,
            nullptr, ctxp, NQ, NQ);
        gemm_tc<4,64><<<gSQ64, 256, GSM4_64>>>(ctxp,
            wp + ((size_t)OFF_SAWO + ((size_t)l << 16)) * 4,
            sa_bo + (size_t)l * EE,
            sub, nullptr, nullptr, nullptr, MQ, 256, 256, 0, 0, 0);
        add_ln_kernel<<<MQ, 256>>>(t, sub, ln1g + (size_t)l*EE, ln1b + (size_t)l*EE,
                                   t, tp);

        /* cross-attention (K/V precomputed) */
        gemm_tc<4,64><<<gSQ64, 256, GSM4_64>>>(tp,
            wp + ((size_t)OFF_CAWQ + ((size_t)l << 16)) * 4,
            ca_bq + (size_t)l * EE,
            nullptr, nullptr, cqh, cql, MQ, 256, 256, 0, 256, 0);
        attn_mma<<<gattn, 256, ATT_SMEM>>>(
            cqh, cql, 256,
            kvh + (size_t)l * 256, kvl + (size_t)l * 256, 3072,
            kvh + 1536 + (size_t)l * 256, 3072,
            maskb, ctxp, NQ, NKK);
        gemm_tc<4,64><<<gSQ64, 256, GSM4_64>>>(ctxp,
            wp + ((size_t)OFF_CAWO + ((size_t)l << 16)) * 4,
            ca_bo + (size_t)l * EE,
            sub, nullptr, nullptr, nullptr, MQ, 256, 256, 0, 0, 0);
        add_ln_kernel<<<MQ, 256>>>(t, sub, ln2g + (size_t)l*EE, ln2b + (size_t)l*EE,
                                   t, tp);

        /* feed-forward */
        gemm_tc<3,128><<<gF1, 256, GSM3_128>>>(tp,
            wp + ((size_t)OFF_FW1 + (size_t)l * 524288) * 4,
            f_b1 + (size_t)l * FFDIM,
            nullptr, ffp, nullptr, nullptr, MQ, 2048, 256, 1, 0, 2048);
        gemm_tc<4,64><<<gSQ64, 256, GSM4_64>>>(ffp,
            wp + ((size_t)OFF_FW2 + (size_t)l * 524288) * 4,
            f_b2 + (size_t)l * EE,
            sub, nullptr, nullptr, nullptr, MQ, 256, 2048, 0, 0, 0);
        add_ln_kernel<<<MQ, 256>>>(t, sub, ln3g + (size_t)l*EE, ln3b + (size_t)l*EE,
                                   t, tp);
    }

    add_ln_kernel<<<MQ, 256>>>(t, nullptr, lnfg, lnfb, (float*)d_out, nullptr);
}

// round 17
// speedup vs baseline: 1.0592x; 1.0007x over previous
#include <cuda_runtime.h>
#include <cuda_bf16.h>
#include <cuda_fp16.h>
#include <math.h>
#include <stdint.h>

#define BB 8
#define NQ 300
#define NKK 4096
#define EE 256
#define HH 8
#define DD 32
#define FFDIM 2048
#define LL 6
#define MQ (BB*NQ)      /* 2400 */
#define MK (BB*NKK)     /* 32768 */
#define MASKN (BB*NQ*NKK)
#define MASKW (MASKN/32)
#define ATT_SCALE 0.17677669529663687f  /* 32^-0.5 */

#if defined(__CUDA_ARCH_FEAT_SM103_ALL) || defined(__CUDA_ARCH_FEAT_SM100_ALL) || \
    (defined(__CUDA_ARCH_SPECIFIC__) && (__CUDA_ARCH_SPECIFIC__ == 1030 || __CUDA_ARCH_SPECIFIC__ == 1000))
#define HAS_TC 1
#else
#define HAS_TC 0
#endif

/* weight bank cumulative offsets (elements).
   [OFF_KV, OFF_CAWO) = combined cross-attn K/V weights:
   3072 rows x 256 = [K_l0..K_l5, V_l0..V_l5]. */
#define OFF_QKV   0
#define OFF_SAWO  1179648
#define OFF_CAWQ  1572864
#define OFF_KV    1966080
#define OFF_CAWO  2752512
#define OFF_FW1   3145728
#define OFF_FW2   6291456
#define WTOT      9437184

#define SWZ128(o) ((o) ^ (((o) >> 3) & 0x70))

/* packed operand layout: 16KB image per (tile128, kchunk32); row = [32 hi | 32 lo] bf16 */
__device__ __host__ __forceinline__ size_t pk_img(int m, int k, int K)
{
    return ((size_t)(m >> 7) * (K >> 5) + (k >> 5)) * 16384;
}
__device__ __host__ __forceinline__ uint32_t pk_off(int m, int k)
{
    return (uint32_t)((m & 127) * 128 + ((k & 31) >> 3) * 16 + (k & 7) * 2);
}

/* ------------ scratch (static device allocations only) ------------ */
__device__ __align__(256) float g_t[MQ*EE];
__device__ __align__(256) float g_sub[MQ*EE];
__device__ __align__(256) float g_kvbias[3072];
__device__ __align__(256) uint32_t g_maskbits[MASKW];
__device__ __align__(256) char g_wp[(size_t)WTOT*4];      /* packed weights (hi+lo) */
__device__ __align__(256) char g_tp[19*8*16384];          /* packed t    (K=256)   */
__device__ __align__(256) char g_ctxp[19*8*16384];        /* packed ctx  (K=256)   */
__device__ __align__(256) char g_memp[(size_t)256*8*16384];/* packed mem (K=256)   */
__device__ __align__(256) char g_ffp[(size_t)19*64*16384]; /* packed ff  (K=2048)  */
__device__ __align__(256) __half g_qkvh[MQ*3*EE], g_qkvl[MQ*3*EE];
__device__ __align__(256) __half g_cqh[MQ*EE], g_cql[MQ*EE];
__device__ __align__(256) __half g_kvh[(size_t)MK*3072];  /* cols [0,1536)=K hi, [1536,3072)=V */
__device__ __align__(256) __half g_kvl[(size_t)MK*3072];  /* K lo */

#define G_HDR 1024

#if HAS_TC
__device__ __forceinline__ uint32_t smem_u32(const void* p)
{
    uint32_t a;
    asm("{ .reg .u64 t; cvta.to.shared.u64 t, %1; cvt.u32.u64 %0, t; }"
        : "=r"(a) : "l"(p));
    return a;
}

static __device__ __forceinline__ uint64_t make_desc_sw128(uint32_t addr)
{
    const uint64_t base =
        (uint64_t(2)  << 61) | (uint64_t(1) << 46) |
        (uint64_t(64) << 32) | (uint64_t(1) << 16);
    return base | ((uint64_t)(addr >> 4) & 0x3FFF);
}

#define TC_ALLOC(sa, n) \
    asm volatile("tcgen05.alloc.cta_group::1.sync.aligned.shared::cta.b32 [%0], %1;" \
                 :: "r"(sa), "r"((uint32_t)(n)) : "memory")
#define TC_RELINQ() \
    asm volatile("tcgen05.relinquish_alloc_permit.cta_group::1.sync.aligned;")
#define TC_DEALLOC(t, n) \
    asm volatile("tcgen05.dealloc.cta_group::1.sync.aligned.b32 %0, %1;" :: "r"(t), "r"((uint32_t)(n)))
#define TC_COMMIT(mb) \
    asm volatile("tcgen05.commit.cta_group::1.mbarrier::arrive::one.shared::cluster.b64 [%0];" \
                 :: "r"(mb) : "memory")
#define TC_FENCE_AFTER()  asm volatile("tcgen05.fence::after_thread_sync;" ::: "memory")
#define TC_WAIT_LD()      asm volatile("tcgen05.wait::ld.sync.aligned;" ::: "memory")
#define MBAR_INVAL(mb) \
    asm volatile("mbarrier.inval.shared.b64 [%0];" :: "r"(mb) : "memory")
#define MBAR_INIT(mb, cnt) \
    asm volatile("mbarrier.init.shared.b64 [%0], %1;" :: "r"(mb), "r"((uint32_t)(cnt)) : "memory")
#define MBAR_ARRIVE_TX(mb, n) \
    asm volatile("mbarrier.arrive.expect_tx.shared.b64 _, [%0], %1;" \
                 :: "r"(mb), "r"((uint32_t)(n)) : "memory")
#define BULK_G2S(dst, src, n, mb) \
    asm volatile("cp.async.bulk.shared::cluster.global.mbarrier::complete_tx::bytes [%0], [%1], %2, [%3];" \
                 :: "r"(dst), "l"(src), "r"((uint32_t)(n)), "r"(mb) : "memory")
#define MBAR_WAIT(mb, ph) do {                                                   \
    uint32_t _mb = (mb), _ph = (ph), _done;                                      \
    asm volatile(                                                                \
        "{\n\t.reg .pred p;\n\t"                                                 \
        "mbarrier.try_wait.parity.acquire.cta.shared::cta.b64 p, [%1], %2;\n\t"  \
        "selp.b32 %0, 1, 0, p;\n\t}"                                             \
        : "=r"(_done) : "r"(_mb), "r"(_ph) : "memory");                          \
    if (!_done) {                                                                \
        asm volatile(                                                            \
            "{\n\t.reg .pred P1;\n\t"                                            \
            "WL_%=:\n\t"                                                         \
            "mbarrier.try_wait.parity.acquire.cta.shared::cta.b64 P1, [%0], %1, 0x989680;\n\t" \
            "@P1 bra.uni WD_%=;\n\t"                                             \
            "bra.uni WL_%=;\n\t"                                                 \
            "WD_%=:\n\t}"                                                        \
            :: "r"(_mb), "r"(_ph) : "memory");                                   \
    }                                                                            \
} while (0)

__device__ __forceinline__ void tc_mma_f16_ss(
    uint32_t d_tmem, uint64_t a_desc, uint64_t b_desc, uint32_t idesc, uint32_t en)
{
    asm volatile(
        "{\n\t.reg .pred p;\n\t"
        "setp.ne.u32 p, %5, 0;\n\t"
        "tcgen05.mma.cta_group::1.kind::f16 [%0], %1, %2, %3, {%4,%4,%4,%4}, p;\n\t}"
        :: "r"(d_tmem), "l"(a_desc), "l"(b_desc), "r"(idesc), "r"(0u), "r"(en)
        : "memory");
}

#define TC_LD_X32(r, ta) \
    asm volatile( \
        "tcgen05.ld.sync.aligned.32x32b.x32.b32 " \
        "{%0, %1, %2, %3, %4, %5, %6, %7, " \
        " %8, %9, %10, %11, %12, %13, %14, %15, " \
        " %16, %17, %18, %19, %20, %21, %22, %23, " \
        " %24, %25, %26, %27, %28, %29, %30, %31}, [%32];" \
        : "=r"((r)[0]),  "=r"((r)[1]),  "=r"((r)[2]),  "=r"((r)[3]), \
          "=r"((r)[4]),  "=r"((r)[5]),  "=r"((r)[6]),  "=r"((r)[7]), \
          "=r"((r)[8]),  "=r"((r)[9]),  "=r"((r)[10]), "=r"((r)[11]), \
          "=r"((r)[12]), "=r"((r)[13]), "=r"((r)[14]), "=r"((r)[15]), \
          "=r"((r)[16]), "=r"((r)[17]), "=r"((r)[18]), "=r"((r)[19]), \
          "=r"((r)[20]), "=r"((r)[21]), "=r"((r)[22]), "=r"((r)[23]), \
          "=r"((r)[24]), "=r"((r)[25]), "=r"((r)[26]), "=r"((r)[27]), \
          "=r"((r)[28]), "=r"((r)[29]), "=r"((r)[30]), "=r"((r)[31]) \
        : "r"(ta))
#endif /* HAS_TC */

/* ======================= GEMM =======================
   C = A @ W^T + bias with pre-packed bf16 hi/lo operands; hh+hl+lh in fp32 TMEM.
   128 x NT CTA tile (NT in {64,128}; M stays 128 because M=64 changes the
   tcgen05 TMEM D layout), K-chunk 32, bulk-copy pipeline driven by ONE thread,
   lookahead STAGES-1.  Outputs: optional f32, packed bf16, f16 hi(/lo). */
template<int STAGES, int NT>
__global__ __launch_bounds__(256) void gemm_tc(
    const char* __restrict__ Ap, const char* __restrict__ Wp,
    const float* __restrict__ bias,
    float* __restrict__ Cf, char* __restrict__ Cbp,
    __half* __restrict__ Cfh, __half* __restrict__ Cfl,
    int M, int N, int K, int relu, int lo_ncols, int cbK)
{
#if HAS_TC
    extern __shared__ __align__(1024) char smem[];
    uint32_t sb = smem_u32(smem);
    int tid = threadIdx.x, wid = tid >> 5, lane = tid & 31;
    int mBase = blockIdx.y * 128, nBase = blockIdx.x * NT;
    int nch = K >> 5;
    const int LA = STAGES - 1;
    const int ABYTES = 16384;
    const int WBYTES = NT * 128;
    const int SBYTES = ABYTES + WBYTES;
    const uint32_t IDESC = (1u << 4) | (1u << 7) | (1u << 10) |
                           ((uint32_t)(NT / 8) << 17) | (8u << 24);

    if (wid == 0) {
        TC_ALLOC(sb, NT);
        TC_RELINQ();
    }
    __syncthreads();
    uint32_t tmem;
    asm volatile("ld.shared.b32 %0, [%1];" : "=r"(tmem) : "r"(sb));
    if (tid == 0) {
        #pragma unroll
        for (int s = 0; s < STAGES; s++) {
            MBAR_INIT(sb + 8 + s * 8, 1);    /* full[s]    */
            MBAR_INIT(sb + 64 + s * 8, 1);   /* mmaDone[s] */
        }
    }
    __syncthreads();

    if (tid == 0) {
        const char* Abase = Ap + (size_t)blockIdx.y * nch * 16384;
        const char* Wbase = Wp + (size_t)(nBase >> 7) * nch * 16384
                               + (uint32_t)(nBase & 127) * 128;
        #pragma unroll
        for (int p = 0; p < LA; p++) {
            if (p >= nch) break;
            uint32_t st = sb + G_HDR + p * SBYTES;
            MBAR_ARRIVE_TX(sb + 8 + p * 8, SBYTES);
            BULK_G2S(st,          Abase + (size_t)p * 16384, ABYTES, sb + 8 + p * 8);
            BULK_G2S(st + ABYTES, Wbase + (size_t)p * 16384, WBYTES, sb + 8 + p * 8);
        }
        for (int ch = 0; ch < nch; ch++) {
            int s = ch % STAGES;
            MBAR_WAIT(sb + 8 + s * 8, (uint32_t)((ch / STAGES) & 1));
            uint32_t stb = sb + G_HDR + s * SBYTES;
            uint64_t dA = make_desc_sw128(stb);
            uint64_t dW = make_desc_sw128(stb + ABYTES);
            #pragma unroll
            for (int ks = 0; ks < 2; ks++) {
                uint64_t o = (uint64_t)(ks * 2);
                tc_mma_f16_ss(tmem, dA + o,     dW + o,     IDESC,
                              (ch == 0 && ks == 0) ? 0u : 1u);
                tc_mma_f16_ss(tmem, dA + o,     dW + 4 + o, IDESC, 1u);
                tc_mma_f16_ss(tmem, dA + 4 + o, dW + o,     IDESC, 1u);
            }
            TC_COMMIT(sb + 64 + s * 8);
            int pre = ch + LA;
            if (pre < nch) {
                int sp = pre % STAGES;
                int tgt = pre - STAGES;
                if (tgt >= 0)
                    MBAR_WAIT(sb + 64 + sp * 8, (uint32_t)((tgt / STAGES) & 1));
                uint32_t stp = sb + G_HDR + sp * SBYTES;
                MBAR_ARRIVE_TX(sb + 8 + sp * 8, SBYTES);
                BULK_G2S(stp,          Abase + (size_t)pre * 16384, ABYTES, sb + 8 + sp * 8);
                BULK_G2S(stp + ABYTES, Wbase + (size_t)pre * 16384, WBYTES, sb + 8 + sp * 8);
            }
        }
        MBAR_WAIT(sb + 64 + ((nch - 1) % STAGES) * 8,
                  (uint32_t)(((nch - 1) / STAGES) & 1));
    }
    __syncthreads();
    TC_FENCE_AFTER();

    if (wid < 4) {
        int row = mBase + wid * 32 + lane;
        bool rv = row < M;
        #pragma unroll
        for (int cb = 0; cb < NT; cb += 32) {
            uint32_t r[32];
            TC_LD_X32(r, tmem + cb);
            TC_WAIT_LD();
            if (rv) {
                #pragma unroll
                for (int c4 = 0; c4 < 32; c4 += 4) {
                    int col = nBase + cb + c4;
                    float4 bv = *(const float4*)&bias[col];
                    float v0 = __uint_as_float(r[c4+0]) + bv.x;
                    float v1 = __uint_as_float(r[c4+1]) + bv.y;
                    float v2 = __uint_as_float(r[c4+2]) + bv.z;
                    float v3 = __uint_as_float(r[c4+3]) + bv.w;
                    if (relu) {
                        v0 = fmaxf(v0, 0.f); v1 = fmaxf(v1, 0.f);
                        v2 = fmaxf(v2, 0.f); v3 = fmaxf(v3, 0.f);
                    }
                    if (Cf)
                        *(float4*)&Cf[(size_t)row * N + col] = make_float4(v0, v1, v2, v3);
                    if (Cbp) {
                        __nv_bfloat16 h0 = __float2bfloat16(v0);
                        __nv_bfloat16 h1 = __float2bfloat16(v1);
                        __nv_bfloat16 h2 = __float2bfloat16(v2);
                        __nv_bfloat16 h3 = __float2bfloat16(v3);
                        char* d = Cbp + pk_img(row, col, cbK);
                        uint32_t off = pk_off(row, col);
                        uint32_t sh = SWZ128(off), sl = SWZ128(off + 64);
                        *(__nv_bfloat162*)(d + sh)     = __nv_bfloat162(h0, h1);
                        *(__nv_bfloat162*)(d + sh + 4) = __nv_bfloat162(h2, h3);
                        *(__nv_bfloat162*)(d + sl) = __nv_bfloat162(
                            __float2bfloat16(v0 - __bfloat162float(h0)),
                            __float2bfloat16(v1 - __bfloat162float(h1)));
                        *(__nv_bfloat162*)(d + sl + 4) = __nv_bfloat162(
                            __float2bfloat16(v2 - __bfloat162float(h2)),
                            __float2bfloat16(v3 - __bfloat162float(h3)));
                    }
                    if (Cfh) {
                        __half h0 = __float2half_rn(v0), h1 = __float2half_rn(v1);
                        __half h2 = __float2half_rn(v2), h3 = __float2half_rn(v3);
                        *(__half2*)&Cfh[(size_t)row * N + col]     = __half2(h0, h1);
                        *(__half2*)&Cfh[(size_t)row * N + col + 2] = __half2(h2, h3);
                        if (Cfl && col < lo_ncols) {
                            *(__half2*)&Cfl[(size_t)row * N + col] = __half2(
                                __float2half_rn(v0 - __half2float(h0)),
                                __float2half_rn(v1 - __half2float(h1)));
                            *(__half2*)&Cfl[(size_t)row * N + col + 2] = __half2(
                                __float2half_rn(v2 - __half2float(h2)),
                                __float2half_rn(v3 - __half2float(h3)));
                        }
                    }
                }
            }
        }
    }
    __syncthreads();
    if (tid == 0) {
        #pragma unroll
        for (int s = 0; s < STAGES; s++) {
            MBAR_INVAL(sb + 8 + s * 8);
            MBAR_INVAL(sb + 64 + s * 8);
        }
    }
    if (wid == 0) TC_DEALLOC(tmem, NT);
#else
    /* SIMT fallback for the non-accelerated gencode pass (never runs) */
    int tid = threadIdx.x;
    int mBase = blockIdx.y * 128, nBase = blockIdx.x * NT;
    for (int u = tid; u < 128 * NT; u += 256) {
        int row = mBase + u / NT;
        int col = nBase + u % NT;
        if (row >= M) continue;
        float acc = 0.f;
        for (int k = 0; k < K; k++) {
            const char* da = Ap + pk_img(row, k, K);
            uint32_t oa = pk_off(row, k);
            float a = __bfloat162float(*(const __nv_bfloat16*)(da + SWZ128(oa))) +
                      __bfloat162float(*(const __nv_bfloat16*)(da + SWZ128(oa + 64)));
            const char* dw = Wp + pk_img(col, k, K);
            uint32_t ow = pk_off(col, k);
            float w = __bfloat162float(*(const __nv_bfloat16*)(dw + SWZ128(ow))) +
                      __bfloat162float(*(const __nv_bfloat16*)(dw + SWZ128(ow + 64)));
            acc += a * w;
        }
        float v = acc + bias[col];
        if (relu) v = fmaxf(v, 0.f);
        if (Cf) Cf[(size_t)row * N + col] = v;
        if (Cbp) {
            __nv_bfloat16 h = __float2bfloat16(v);
            char* d = Cbp + pk_img(row, col, cbK);
            uint32_t off = pk_off(row, col);
            *(__nv_bfloat16*)(d + SWZ128(off)) = h;
            *(__nv_bfloat16*)(d + SWZ128(off + 64)) =
                __float2bfloat16(v - __bfloat162float(h));
        }
        if (Cfh) {
            __half h = __float2half_rn(v);
            Cfh[(size_t)row * N + col] = h;
            if (Cfl && col < lo_ncols)
                Cfl[(size_t)row * N + col] = __float2half_rn(v - __half2float(h));
        }
    }
#endif
}

/* ================= tensor-core flash attention (mma.sync fp16) ================= */
#define AT_QH 0
#define AT_QL 5120
#define AT_KH 10240
#define AT_KL 20480
#define AT_P  10240
#define AT_VT 30720
#define AT_S  39424
#define AT_M  73216
#define AT_L  73472
#define AT_AL 73728
#define ATT_SMEM 73984

#define MMA16816(c, a, b0, b1) \
    asm volatile("mma.sync.aligned.m16n8k16.row.col.f32.f16.f16.f32 " \
        "{%0,%1,%2,%3}, {%4,%5,%6,%7}, {%8,%9}, {%0,%1,%2,%3};" \
        : "+f"((c)[0]), "+f"((c)[1]), "+f"((c)[2]), "+f"((c)[3]) \
        : "r"((a)[0]), "r"((a)[1]), "r"((a)[2]), "r"((a)[3]), "r"(b0), "r"(b1))

__global__ __launch_bounds__(256) void attn_mma(
    const __half* __restrict__ qh_g, const __half* __restrict__ ql_g, int qstride,
    const __half* __restrict__ kh_g, const __half* __restrict__ kl_g, int kstride,
    const __half* __restrict__ vh_g, int vstride,
    const uint32_t* __restrict__ maskb,
    char* __restrict__ outp,
    int nq, int nk)
{
    extern __shared__ __align__(16) char sm[];
    __half* Qh = (__half*)(sm + AT_QH);
    __half* Ql = (__half*)(sm + AT_QL);
    __half* Kh = (__half*)(sm + AT_KH);
    __half* Kl = (__half*)(sm + AT_KL);
    __half* P  = (__half*)(sm + AT_P);
    __half* Vt = (__half*)(sm + AT_VT);
    float*  S  = (float*)(sm + AT_S);
    float*  mS = (float*)(sm + AT_M);
    float*  lS = (float*)(sm + AT_L);
    float*  aS = (float*)(sm + AT_AL);

    int tid = threadIdx.x;
    int wid = tid >> 5, lane = tid & 31;
    int gid = lane >> 2, tig = lane & 3;
    int wM = wid & 3, wHalf = wid >> 2;
    int b = blockIdx.z, hd = blockIdx.y;
    int qt = blockIdx.x * 64;

    {
        int row = tid >> 2, d8 = (tid & 3) * 8;
        uint4 vq = make_uint4(0,0,0,0), vl4 = make_uint4(0,0,0,0);
        if (qt + row < nq) {
            size_t base = ((size_t)(b * nq + qt + row)) * qstride + hd * DD + d8;
            vq  = *(const uint4*)&qh_g[base];
            vl4 = *(const uint4*)&ql_g[base];
        }
        *(uint4*)&Qh[row * 40 + d8] = vq;
        *(uint4*)&Ql[row * 40 + d8] = vl4;
    }
    if (tid < 64) { mS[tid] = -INFINITY; lS[tid] = 0.f; }
    __syncthreads();

    uint32_t aQh[2][4], aQl[2][4];
    int ar0 = wM * 16 + gid, ar1 = ar0 + 8;
    #pragma unroll
    for (int ks = 0; ks < 2; ks++) {
        int c0 = ks * 16 + 2 * tig;
        aQh[ks][0] = *(uint32_t*)&Qh[ar0 * 40 + c0];
        aQh[ks][1] = *(uint32_t*)&Qh[ar1 * 40 + c0];
        aQh[ks][2] = *(uint32_t*)&Qh[ar0 * 40 + c0 + 8];
        aQh[ks][3] = *(uint32_t*)&Qh[ar1 * 40 + c0 + 8];
        aQl[ks][0] = *(uint32_t*)&Ql[ar0 * 40 + c0];
        aQl[ks][1] = *(uint32_t*)&Ql[ar1 * 40 + c0];
        aQl[ks][2] = *(uint32_t*)&Ql[ar0 * 40 + c0 + 8];
        aQl[ks][3] = *(uint32_t*)&Ql[ar1 * 40 + c0 + 8];
    }

    float oc[4][4] = {};

    for (int kc = 0; kc < nk; kc += 128) {
        __syncthreads();

        #pragma unroll
        for (int i = 0; i < 2; i++) {
            int idx = tid + i * 256;
            int row = idx >> 2, d8 = (idx & 3) * 8;
            int kg = kc + row;
            uint4 a = make_uint4(0,0,0,0), c4 = make_uint4(0,0,0,0), vv = make_uint4(0,0,0,0);
            if (kg < nk) {
                size_t base = ((size_t)(b * nk + kg)) * kstride + hd * DD + d8;
                a  = *(const uint4*)&kh_g[base];
                c4 = *(const uint4*)&kl_g[base];
                size_t vb = ((size_t)(b * nk + kg)) * vstride + hd * DD + d8;
                vv = *(const uint4*)&vh_g[vb];
            }
            *(uint4*)&Kh[row * 40 + d8] = a;
            *(uint4*)&Kl[row * 40 + d8] = c4;
            const __half* hp = (const __half*)&vv;
            #pragma unroll
            for (int e = 0; e < 8; e++)
                Vt[(d8 + e) * 136 + row] = hp[e];
        }
        __syncthreads();

        #pragma unroll
        for (int nt = 0; nt < 8; nt++) {
            float c[4] = {0.f, 0.f, 0.f, 0.f};
            int bn = wHalf * 64 + nt * 8 + gid;
            #pragma unroll
            for (int ks = 0; ks < 2; ks++) {
                int c0 = ks * 16 + 2 * tig;
                uint32_t bh0 = *(uint32_t*)&Kh[bn * 40 + c0];
                uint32_t bh1 = *(uint32_t*)&Kh[bn * 40 + c0 + 8];
                uint32_t bl0 = *(uint32_t*)&Kl[bn * 40 + c0];
                uint32_t bl1 = *(uint32_t*)&Kl[bn * 40 + c0 + 8];
                MMA16816(c, aQh[ks], bh0, bh1);
                MMA16816(c, aQl[ks], bh0, bh1);
                MMA16816(c, aQh[ks], bl0, bl1);
            }
            int sc = wHalf * 64 + nt * 8 + 2 * tig;
            S[(wM * 16 + gid) * 132 + sc]     = c[0] * ATT_SCALE;
            S[(wM * 16 + gid) * 132 + sc + 1] = c[1] * ATT_SCALE;
            S[(wM * 16 + gid + 8) * 132 + sc]     = c[2] * ATT_SCALE;
            S[(wM * 16 + gid + 8) * 132 + sc + 1] = c[3] * ATT_SCALE;
        }
        __syncthreads();

        {
            int r = tid >> 2, j = tid & 3;
            int qrow = qt + r;
            bool rowValid = qrow < nq;
            uint32_t word = 0xFFFFFFFFu;
            if (!rowValid) word = 0u;
            else if (maskb) word = maskb[(size_t)(b * nq + qrow) * (nk >> 5) + (kc >> 5) + j];
            float mx = -INFINITY;
            #pragma unroll
            for (int e = 0; e < 32; e++) {
                int col = j * 32 + e;
                float s = S[r * 132 + col];
                bool ok = ((word >> e) & 1u) && (kc + col < nk);
                s = ok ? s : -INFINITY;
                S[r * 132 + col] = s;
                mx = fmaxf(mx, s);
            }
            mx = fmaxf(mx, __shfl_xor_sync(0xffffffffu, mx, 1));
            mx = fmaxf(mx, __shfl_xor_sync(0xffffffffu, mx, 2));
            float mOld = mS[r];
            float mNew = fmaxf(mOld, mx);
            float mUse = fmaxf(mNew, -1e30f);
            float psum = 0.f;
            #pragma unroll
            for (int e = 0; e < 32; e++) {
                int col = j * 32 + e;
                float p = __expf(S[r * 132 + col] - mUse);
                P[r * 136 + col] = __float2half_rn(p);
                psum += p;
            }
            psum += __shfl_xor_sync(0xffffffffu, psum, 1);
            psum += __shfl_xor_sync(0xffffffffu, psum, 2);
            if (j == 0) {
                float alpha = __expf(mOld - mUse);
                aS[r] = alpha;
                lS[r] = lS[r] * alpha + psum;
                mS[r] = mNew;
            }
        }
        __syncthreads();

        {
            float f0 = aS[wM * 16 + gid];
            float f1 = aS[wM * 16 + 8 + gid];
            #pragma unroll
            for (int nt = 0; nt < 4; nt++) {
                oc[nt][0] *= f0; oc[nt][1] *= f0;
                oc[nt][2] *= f1; oc[nt][3] *= f1;
            }
            #pragma unroll
            for (int ks = 0; ks < 4; ks++) {
                int kbase = wHalf * 64 + ks * 16;
                uint32_t pa[4];
                pa[0] = *(uint32_t*)&P[(wM * 16 + gid) * 136 + kbase + 2 * tig];
                pa[1] = *(uint32_t*)&P[(wM * 16 + 8 + gid) * 136 + kbase + 2 * tig];
                pa[2] = *(uint32_t*)&P[(wM * 16 + gid) * 136 + kbase + 2 * tig + 8];
                pa[3] = *(uint32_t*)&P[(wM * 16 + 8 + gid) * 136 + kbase + 2 * tig + 8];
                #pragma unroll
                for (int nt = 0; nt < 4; nt++) {
                    uint32_t b0 = *(uint32_t*)&Vt[(nt * 8 + gid) * 136 + kbase + 2 * tig];
                    uint32_t b1 = *(uint32_t*)&Vt[(nt * 8 + gid) * 136 + kbase + 2 * tig + 8];
                    MMA16816(oc[nt], pa, b0, b1);
                }
            }
        }
    }
    __syncthreads();

    float* CB = S;
    if (wHalf == 1) {
        #pragma unroll
        for (int nt = 0; nt < 4; nt++) {
            int cc = nt * 8 + 2 * tig;
            CB[(wM * 16 + gid) * 36 + cc]     = oc[nt][0];
            CB[(wM * 16 + gid) * 36 + cc + 1] = oc[nt][1];
            CB[(wM * 16 + 8 + gid) * 36 + cc]     = oc[nt][2];
            CB[(wM * 16 + 8 + gid) * 36 + cc + 1] = oc[nt][3];
        }
    }
    __syncthreads();
    if (wHalf == 0) {
        int r0 = wM * 16 + gid, r1 = r0 + 8;
        float il0 = 1.f / lS[r0], il1 = 1.f / lS[r1];
        bool v0r = (qt + r0) < nq, v1r = (qt + r1) < nq;
        #pragma unroll
        for (int nt = 0; nt < 4; nt++) {
            int cc = nt * 8 + 2 * tig;
            float x0 = (oc[nt][0] + CB[r0 * 36 + cc]) * il0;
            float x1 = (oc[nt][1] + CB[r0 * 36 + cc + 1]) * il0;
            float x2 = (oc[nt][2] + CB[r1 * 36 + cc]) * il1;
            float x3 = (oc[nt][3] + CB[r1 * 36 + cc + 1]) * il1;
            int col = hd * DD + cc;
            if (v0r) {
                int grow = b * nq + qt + r0;
                __nv_bfloat16 h0 = __float2bfloat16(x0), h1 = __float2bfloat16(x1);
                char* d = outp + pk_img(grow, col, 256);
                uint32_t off = pk_off(grow, col);
                *(__nv_bfloat162*)(d + SWZ128(off)) = __nv_bfloat162(h0, h1);
                *(__nv_bfloat162*)(d + SWZ128(off + 64)) = __nv_bfloat162(
                    __float2bfloat16(x0 - __bfloat162float(h0)),
                    __float2bfloat16(x1 - __bfloat162float(h1)));
            }
            if (v1r) {
                int grow = b * nq + qt + r1;
                __nv_bfloat16 h2 = __float2bfloat16(x2), h3 = __float2bfloat16(x3);
                char* d = outp + pk_img(grow, col, 256);
                uint32_t off = pk_off(grow, col);
                *(__nv_bfloat162*)(d + SWZ128(off)) = __nv_bfloat162(h2, h3);
                *(__nv_bfloat162*)(d + SWZ128(off + 64)) = __nv_bfloat162(
                    __float2bfloat16(x2 - __bfloat162float(h2)),
                    __float2bfloat16(x3 - __bfloat162float(h3)));
            }
        }
    }
}

/* ---------------- setup kernels ---------------- */
__global__ void mask_bits_kernel(const void* __restrict__ raw,
                                 uint32_t* __restrict__ out)
{
    __shared__ int c1, c3;
    int tid = threadIdx.x;
    if (tid == 0) { c1 = 0; c3 = 0; }
    __syncthreads();
    const unsigned char* m = (const unsigned char*)raw;
    if (m[4 * tid + 1]) atomicAdd(&c1, 1);
    if (m[4 * tid + 3]) atomicAdd(&c3, 1);
    __syncthreads();
    int mode = (c1 > 0) ? 0 : ((c3 > 0) ? 2 : 1);

    int w = blockIdx.x * blockDim.x + tid;
    if (w >= MASKW) return;
    size_t base = (size_t)w * 32;
    uint32_t bits = 0;
    if (mode == 0) {
        const unsigned char* p = (const unsigned char*)raw + base;
        #pragma unroll
        for (int e = 0; e < 32; e++) bits |= (uint32_t)(p[e] != 0) << e;
    } else if (mode == 1) {
        const int* p = (const int*)raw + base;
        #pragma unroll
        for (int e = 0; e < 32; e++) bits |= (uint32_t)(p[e] != 0) << e;
    } else {
        const float* p = (const float*)raw + base;
        #pragma unroll
        for (int e = 0; e < 32; e++) bits |= (uint32_t)(p[e] != 0.f) << e;
    }
    out[w] = bits;
}

__device__ __forceinline__ void pk_write4(char* dstbase, int n, int k, int K, float4 x)
{
    __nv_bfloat16 h0 = __float2bfloat16(x.x), h1 = __float2bfloat16(x.y);
    __nv_bfloat16 h2 = __float2bfloat16(x.z), h3 = __float2bfloat16(x.w);
    char* d = dstbase + pk_img(n, k, K);
    uint32_t off = pk_off(n, k);
    uint32_t sh = SWZ128(off), sl = SWZ128(off + 64);
    *(__nv_bfloat162*)(d + sh)     = __nv_bfloat162(h0, h1);
    *(__nv_bfloat162*)(d + sh + 4) = __nv_bfloat162(h2, h3);
    *(__nv_bfloat162*)(d + sl) = __nv_bfloat162(
        __float2bfloat16(x.x - __bfloat162float(h0)),
        __float2bfloat16(x.y - __bfloat162float(h1)));
    *(__nv_bfloat162*)(d + sl + 4) = __nv_bfloat162(
        __float2bfloat16(x.z - __bfloat162float(h2)),
        __float2bfloat16(x.w - __bfloat162float(h3)));
}

__global__ void convert_hilo_all(const float* __restrict__ tgt,
                                 const float* __restrict__ memory)
{
    int i = blockIdx.x * blockDim.x + threadIdx.x;
    int idx = i * 4;
    if (idx < MQ * EE) {
        float4 x = *(const float4*)&tgt[idx];
        pk_write4(g_tp, idx >> 8, idx & 255, 256, x);
    } else if (idx < MQ * EE + MK * EE) {
        int r = idx - MQ * EE;
        float4 x = *(const float4*)&memory[r];
        pk_write4(g_memp, r >> 8, r & 255, 256, x);
    }
}

/* weight packing; [OFF_KV, OFF_CAWO) re-laid-out as 3072 rows = [K_l0..K_l5, V_l0..V_l5] */
__global__ void convert_weights(
    const float* __restrict__ w_qkv, const float* __restrict__ w_sawo,
    const float* __restrict__ w_caq, const float* __restrict__ wk,
    const float* __restrict__ wv,   const float* __restrict__ w_cawo,
    const float* __restrict__ w_f1, const float* __restrict__ w_f2)
{
    int i = blockIdx.x * blockDim.x + threadIdx.x;
    int j = i * 4;
    if (j >= WTOT) return;
    const float* ptr;
    size_t dstbase;
    int n, k, K;
    if (j >= OFF_KV && j < OFF_CAWO) {
        int rel = j - OFF_KV;
        int r = rel >> 8, c = rel & 255;
        if (r < 1536) {
            int l = r >> 8;
            ptr = wk + (size_t)l * 65536 + (size_t)(r & 255) * 256 + c;
        } else {
            int r2 = r - 1536;
            int l = r2 >> 8;
            ptr = wv + (size_t)l * 65536 + (size_t)(r2 & 255) * 256 + c;
        }
        dstbase = (size_t)OFF_KV * 4; n = r; k = c; K = 256;
    } else if (j < OFF_SAWO) {
        int rel = j - OFF_QKV;
        ptr = w_qkv + rel;
        int l = rel / 196608, r = rel % 196608;
        dstbase = ((size_t)OFF_QKV + (size_t)l * 196608) * 4;
        n = r >> 8; k = r & 255; K = 256;
    } else if (j < OFF_CAWQ) {
        int rel = j - OFF_SAWO;
        ptr = w_sawo + rel;
        int l = rel >> 16, r = rel & 65535;
        dstbase = ((size_t)OFF_SAWO + ((size_t)l << 16)) * 4;
        n = r >> 8; k = r & 255; K = 256;
    } else if (j < OFF_KV) {
        int rel = j - OFF_CAWQ;
        ptr = w_caq + rel;
        int l = rel >> 16, r = rel & 65535;
        dstbase = ((size_t)OFF_CAWQ + ((size_t)l << 16)) * 4;
        n = r >> 8; k = r & 255; K = 256;
    } else if (j < OFF_FW1) {
        int rel = j - OFF_CAWO;
        ptr = w_cawo + rel;
        int l = rel >> 16, r = rel & 65535;
        dstbase = ((size_t)OFF_CAWO + ((size_t)l << 16)) * 4;
        n = r >> 8; k = r & 255; K = 256;
    } else if (j < OFF_FW2) {
        int rel = j - OFF_FW1;
        ptr = w_f1 + rel;
        int l = rel / 524288, r = rel % 524288;
        dstbase = ((size_t)OFF_FW1 + (size_t)l * 524288) * 4;
        n = r >> 8; k = r & 255; K = 256;
    } else {
        int rel = j - OFF_FW2;
        ptr = w_f2 + rel;
        int l = rel / 524288, r = rel % 524288;
        dstbase = ((size_t)OFF_FW2 + (size_t)l * 524288) * 4;
        n = r / 2048; k = r % 2048; K = 2048;
    }
    float4 x = *(const float4*)ptr;
    pk_write4(g_wp + dstbase, n, k, K, x);
}

/* ------------------- add + LayerNorm (+ optional packed bf16) ------------------- */
__device__ __forceinline__ float block_sum256(float v, float* red)
{
    #pragma unroll
    for (int o = 16; o; o >>= 1) v += __shfl_xor_sync(0xffffffffu, v, o);
    int w = threadIdx.x >> 5;
    if ((threadIdx.x & 31) == 0) red[w] = v;
    __syncthreads();
    if (threadIdx.x < 32) {
        float u = (threadIdx.x < 8) ? red[threadIdx.x] : 0.f;
        #pragma unroll
        for (int o = 4; o; o >>= 1) u += __shfl_xor_sync(0xffffffffu, u, o);
        if (threadIdx.x == 0) red[0] = u;
    }
    __syncthreads();
    float r = red[0];
    __syncthreads();
    return r;
}

__global__ __launch_bounds__(256) void add_ln_kernel(
    const float* __restrict__ x, const float* __restrict__ y,
    const float* __restrict__ g, const float* __restrict__ b,
    float* __restrict__ out, char* __restrict__ op)
{
    __shared__ float red[8];
    int row = blockIdx.x;
    int tid = threadIdx.x;
    float v = x[(size_t)row * EE + tid];
    if (y) v += y[(size_t)row * EE + tid];
    float mean = block_sum256(v, red) * (1.f / EE);
    float diff = v - mean;
    float var = block_sum256(diff * diff, red) * (1.f / EE);
    float r = diff * rsqrtf(var + 1e-5f) * g[tid] + b[tid];
    out[(size_t)row * EE + tid] = r;
    if (op) {
        __nv_bfloat16 h = __float2bfloat16(r);
        char* d = op + pk_img(row, tid, 256);
        uint32_t off = pk_off(row, tid);
        *(__nv_bfloat16*)(d + SWZ128(off)) = h;
        *(__nv_bfloat16*)(d + SWZ128(off + 64)) =
            __float2bfloat16(r - __bfloat162float(h));
    }
}

/* ------------------------------- host side ------------------------------- */
extern "C" void kernel_launch(void* const* d_in, const int* in_sizes, int n_in,
                              void* d_out, int out_size)
{
    const float* tgt      = (const float*)d_in[0];
    const float* memory   = (const float*)d_in[1];
    const void*  maskraw  = d_in[2];
    const float* sa_wqkv  = (const float*)d_in[3];
    const float* sa_bqkv  = (const float*)d_in[4];
    const float* sa_wo    = (const float*)d_in[5];
    const float* sa_bo    = (const float*)d_in[6];
    const float* ca_wq    = (const float*)d_in[7];
    const float* ca_bq    = (const float*)d_in[8];
    const float* ca_wk    = (const float*)d_in[9];
    const float* ca_bk    = (const float*)d_in[10];
    const float* ca_wv    = (const float*)d_in[11];
    const float* ca_bv    = (const float*)d_in[12];
    const float* ca_wo    = (const float*)d_in[13];
    const float* ca_bo    = (const float*)d_in[14];
    const float* f_w1     = (const float*)d_in[15];
    const float* f_b1     = (const float*)d_in[16];
    const float* f_w2     = (const float*)d_in[17];
    const float* f_b2     = (const float*)d_in[18];
    const float* ln1g     = (const float*)d_in[19];
    const float* ln1b     = (const float*)d_in[20];
    const float* ln2g     = (const float*)d_in[21];
    const float* ln2b     = (const float*)d_in[22];
    const float* ln3g     = (const float*)d_in[23];
    const float* ln3b     = (const float*)d_in[24];
    const float* lnfg     = (const float*)d_in[25];
    const float* lnfb     = (const float*)d_in[26];

    float *t, *sub, *kvbias;
    uint32_t* maskb;
    char *wp, *tp, *ctxp, *memp, *ffp;
    __half *qkvh, *qkvl, *cqh, *cql, *kvh, *kvl;
    cudaGetSymbolAddress((void**)&t,      g_t);
    cudaGetSymbolAddress((void**)&sub,    g_sub);
    cudaGetSymbolAddress((void**)&kvbias, g_kvbias);
    cudaGetSymbolAddress((void**)&maskb,  g_maskbits);
    cudaGetSymbolAddress((void**)&wp,     g_wp);
    cudaGetSymbolAddress((void**)&tp,     g_tp);
    cudaGetSymbolAddress((void**)&ctxp,   g_ctxp);
    cudaGetSymbolAddress((void**)&memp,   g_memp);
    cudaGetSymbolAddress((void**)&ffp,    g_ffp);
    cudaGetSymbolAddress((void**)&qkvh,   g_qkvh);
    cudaGetSymbolAddress((void**)&qkvl,   g_qkvl);
    cudaGetSymbolAddress((void**)&cqh,    g_cqh);
    cudaGetSymbolAddress((void**)&cql,    g_cql);
    cudaGetSymbolAddress((void**)&kvh,    g_kvh);
    cudaGetSymbolAddress((void**)&kvl,    g_kvl);

    const int GSM3_128 = G_HDR + 3 * 32768;   /* 99KB: 2 CTAs/SM */
    const int GSM4_128 = G_HDR + 4 * 32768;   /* 132KB: deep lookahead */
    const int GSM4_64  = G_HDR + 4 * 24576;   /* 99KB: 2 CTAs/SM, NT=64 */
    cudaFuncSetAttribute((gemm_tc<3,128>), cudaFuncAttributeMaxDynamicSharedMemorySize, GSM3_128);
    cudaFuncSetAttribute((gemm_tc<4,128>), cudaFuncAttributeMaxDynamicSharedMemorySize, GSM4_128);
    cudaFuncSetAttribute((gemm_tc<4,64>),  cudaFuncAttributeMaxDynamicSharedMemorySize, GSM4_64);
    cudaFuncSetAttribute(attn_mma, cudaFuncAttributeMaxDynamicSharedMemorySize, ATT_SMEM);

    cudaMemcpyAsync(t, tgt, (size_t)MQ * EE * sizeof(float),
                    cudaMemcpyDeviceToDevice, 0);
    cudaMemcpyAsync(kvbias, ca_bk, 1536 * sizeof(float), cudaMemcpyDeviceToDevice, 0);
    cudaMemcpyAsync(kvbias + 1536, ca_bv, 1536 * sizeof(float), cudaMemcpyDeviceToDevice, 0);

    mask_bits_kernel<<<(MASKW + 255) / 256, 256>>>(maskraw, maskb);
    {
        int tot4 = (MQ * EE + MK * EE) / 4;
        convert_hilo_all<<<(tot4 + 255) / 256, 256>>>(tgt, memory);
    }
    convert_weights<<<(WTOT / 4 + 255) / 256, 256>>>(sa_wqkv, sa_wo, ca_wq, ca_wk,
                                                     ca_wv, ca_wo, f_w1, f_w2);

    /* hoisted: ALL cross-attn K/V projections in one launch */
    gemm_tc<3,128><<<dim3(24, 256), 256, GSM3_128>>>(memp, wp + (size_t)OFF_KV * 4, kvbias,
        nullptr, nullptr, kvh, kvl, MK, 3072, 256, 0, 1536, 0);

    dim3 gattn((NQ + 63) / 64, HH, BB);
    dim3 gQKV(6, 19), gSQ64(4, 19), gF1(16, 19);

    for (int l = 0; l < LL; l++) {
        /* self-attention */
        gemm_tc<4,128><<<gQKV, 256, GSM4_128>>>(tp,
            wp + ((size_t)OFF_QKV + (size_t)l * 196608) * 4,
            sa_bqkv + (size_t)l * 768,
            nullptr, nullptr, qkvh, qkvl, MQ, 768, 256, 0, 768, 0);
        attn_mma<<<gattn, 256, ATT_SMEM>>>(
            qkvh, qkvl, 768, qkvh + 256, qkvl + 256, 768, qkvh + 512, 768,
            nullptr, ctxp, NQ, NQ);
        gemm_tc<4,64><<<gSQ64, 256, GSM4_64>>>(ctxp,
            wp + ((size_t)OFF_SAWO + ((size_t)l << 16)) * 4,
            sa_bo + (size_t)l * EE,
            sub, nullptr, nullptr, nullptr, MQ, 256, 256, 0, 0, 0);
        add_ln_kernel<<<MQ, 256>>>(t, sub, ln1g + (size_t)l*EE, ln1b + (size_t)l*EE,
                                   t, tp);

        /* cross-attention (K/V precomputed) */
        gemm_tc<4,64><<<gSQ64, 256, GSM4_64>>>(tp,
            wp + ((size_t)OFF_CAWQ + ((size_t)l << 16)) * 4,
            ca_bq + (size_t)l * EE,
            nullptr, nullptr, cqh, cql, MQ, 256, 256, 0, 256, 0);
        attn_mma<<<gattn, 256, ATT_SMEM>>>(
            cqh, cql, 256,
            kvh + (size_t)l * 256, kvl + (size_t)l * 256, 3072,
            kvh + 1536 + (size_t)l * 256, 3072,
            maskb, ctxp, NQ, NKK);
        gemm_tc<4,64><<<gSQ64, 256, GSM4_64>>>(ctxp,
            wp + ((size_t)OFF_CAWO + ((size_t)l << 16)) * 4,
            ca_bo + (size_t)l * EE,
            sub, nullptr, nullptr, nullptr, MQ, 256, 256, 0, 0, 0);
        add_ln_kernel<<<MQ, 256>>>(t, sub, ln2g + (size_t)l*EE, ln2b + (size_t)l*EE,
                                   t, tp);

        /* feed-forward */
        gemm_tc<3,128><<<gF1, 256, GSM3_128>>>(tp,
            wp + ((size_t)OFF_FW1 + (size_t)l * 524288) * 4,
            f_b1 + (size_t)l * FFDIM,
            nullptr, ffp, nullptr, nullptr, MQ, 2048, 256, 1, 0, 2048);
        gemm_tc<4,64><<<gSQ64, 256, GSM4_64>>>(ffp,
            wp + ((size_t)OFF_FW2 + (size_t)l * 524288) * 4,
            f_b2 + (size_t)l * EE,
            sub, nullptr, nullptr, nullptr, MQ, 256, 2048, 0, 0, 0);
        add_ln_kernel<<<MQ, 256>>>(t, sub, ln3g + (size_t)l*EE, ln3b + (size_t)l*EE,
                                   t, tp);
    }

    add_ln_kernel<<<MQ, 256>>>(t, nullptr, lnfg, lnfb, (float*)d_out, nullptr);
}